// round 8
// baseline (speedup 1.0000x reference)
#include <cuda_runtime.h>
#include <cuda_bf16.h>
#include <cstdint>

#define MAXN 100000

// ---------------- device scratch ----------------
__device__ float g_h[MAXN * 256];            // hidden state fp32
__device__ __nv_bfloat16 g_Ahi[MAXN * 512];  // x hi (bf16), lda=512
__device__ __nv_bfloat16 g_Alo[MAXN * 512];  // x lo
__device__ __nv_bfloat16 g_Hhi[MAXN * 256];  // h hi (bf16), lda=256
__device__ __nv_bfloat16 g_Hlo[MAXN * 256];  // h lo
__device__ __nv_bfloat16 g_Bhi[256 * 512];   // weight operand hi, [n][k]
__device__ __nv_bfloat16 g_Blo[256 * 512];   // weight operand lo

// ---------------- PTX helpers (compute_103-safe) ----------------
__device__ __forceinline__ uint32_t smem_u32(const void* p) {
    uint32_t a;
    asm("{ .reg .u64 t; cvta.to.shared.u64 t, %1; cvt.u32.u64 %0, t; }" : "=r"(a) : "l"(p));
    return a;
}
__device__ __forceinline__ void cp16(uint32_t dst, const void* src) {
    asm volatile("cp.async.cg.shared.global [%0], [%1], 16;" :: "r"(dst), "l"(src));
}
__device__ __forceinline__ void cp_commit() {
    asm volatile("cp.async.commit_group;" ::: "memory");
}
__device__ __forceinline__ void cp_wait1() {
    asm volatile("cp.async.wait_group 1;" ::: "memory");
}
__device__ __forceinline__ void ldm_x4(uint32_t* r, uint32_t addr) {
    asm volatile("ldmatrix.sync.aligned.m8n8.x4.shared.b16 {%0,%1,%2,%3}, [%4];"
        : "=r"(r[0]), "=r"(r[1]), "=r"(r[2]), "=r"(r[3]) : "r"(addr));
}
__device__ __forceinline__ void mma16816(float* c, const uint32_t* a, const uint32_t* b) {
    asm volatile("mma.sync.aligned.m16n8k16.row.col.f32.bf16.bf16.f32 "
        "{%0,%1,%2,%3}, {%4,%5,%6,%7}, {%8,%9}, {%0,%1,%2,%3};"
        : "+f"(c[0]), "+f"(c[1]), "+f"(c[2]), "+f"(c[3])
        : "r"(a[0]), "r"(a[1]), "r"(a[2]), "r"(a[3]), "r"(b[0]), "r"(b[1]));
}

__device__ __forceinline__ void pack8_bf16(const float* v, uint4& H) {
    uint32_t h[4];
    #pragma unroll
    for (int p = 0; p < 4; p++)
        h[p] = (uint32_t)__bfloat16_as_ushort(__float2bfloat16(v[2 * p])) |
               ((uint32_t)__bfloat16_as_ushort(__float2bfloat16(v[2 * p + 1])) << 16);
    H = make_uint4(h[0], h[1], h[2], h[3]);
}

// SMEM per stage (80B row stride): AH @0 (10240), AL @10240, BH @20480 (20480), BL @40960
// Stage size 61440, two stages = 122880. Epilogue Ct float[128][260] = 133120 (reuses all).
#define CT_STRIDE 260
#define DSMEM 133120

// ============ fused GEMM + LN: one CTA owns a full 128-row x 256-col output ============
// C = (Ahi+Alo)[M,K] @ (Bhi+Blo)[256,K]^T + bias, then:
//   RESID=0: h = relu(LN(C));      RESID=1: h = LN(0.5*C + 0.5*h)
// EMIT=1: also write bf16 hi/lo of h into Ohi/Olo (same rows this CTA read -> race-free).
// grid = ceil(M/128), 256 threads (8 warps: 4m x 2n, 32x128 warp tile).
template<int RESID, int EMIT>
__global__ void __launch_bounds__(256, 1) gemm_fused(
    const __nv_bfloat16* __restrict__ Ahi, const __nv_bfloat16* __restrict__ Alo, int lda,
    const __nv_bfloat16* __restrict__ Bhi, const __nv_bfloat16* __restrict__ Blo,
    const float* __restrict__ bias,
    float* __restrict__ H,
    __nv_bfloat16* __restrict__ Ohi, __nv_bfloat16* __restrict__ Olo,
    const float* __restrict__ lng, const float* __restrict__ lnb,
    int M, int K)
{
    extern __shared__ char dsm[];
    __shared__ float biasS[256];
    const int tid = threadIdx.x;
    const int lane = tid & 31, wid = tid >> 5;
    const int wm = wid >> 1, wn = wid & 1;       // 4 x 2 warp grid
    const int row0 = blockIdx.x * 128;
    const int nk = K >> 5;                        // BK=32

    const uint32_t sbase = smem_u32(dsm);
    biasS[tid] = bias[tid];

    // cp.async assignments: A 2 chunks/thread, B 4 chunks/thread (16B each)
    const __nv_bfloat16* aS[2];  const __nv_bfloat16* alS[2];
    const __nv_bfloat16* bS[4];  const __nv_bfloat16* blS[4];
    uint32_t aD[2], bD[4];
    #pragma unroll
    for (int i = 0; i < 2; i++) {
        int cid = tid + i * 256;
        int r = cid >> 2, seg = cid & 3;
        int arow = min(row0 + r, M - 1);
        aS[i]  = Ahi + (long long)arow * lda + seg * 8;
        alS[i] = Alo + (long long)arow * lda + seg * 8;
        aD[i] = (uint32_t)(r * 80 + seg * 16);
    }
    #pragma unroll
    for (int i = 0; i < 4; i++) {
        int cid = tid + i * 256;
        int r = cid >> 2, seg = cid & 3;          // r in 0..255
        bS[i]  = Bhi + (long long)r * K + seg * 8;
        blS[i] = Blo + (long long)r * K + seg * 8;
        bD[i] = (uint32_t)(r * 80 + seg * 16);
    }

    float acc[2][16][4] = {};

    // prologue: stage 0
    {
        uint32_t sb = sbase;
        #pragma unroll
        for (int i = 0; i < 2; i++) {
            cp16(sb + aD[i], aS[i]);
            cp16(sb + 10240 + aD[i], alS[i]);
        }
        #pragma unroll
        for (int i = 0; i < 4; i++) {
            cp16(sb + 20480 + bD[i], bS[i]);
            cp16(sb + 40960 + bD[i], blS[i]);
        }
        cp_commit();
    }

    const uint32_t aoff = (uint32_t)((lane & 15) * 80 + (lane >> 4) * 16);
    const uint32_t boff = (uint32_t)(((lane & 7) + ((lane >> 4) << 3)) * 80 + (((lane >> 3) & 1) << 4));
    const uint32_t awarp = (uint32_t)(wm * 32) * 80;
    const uint32_t bwarp = (uint32_t)(wn * 128) * 80;

    for (int kt = 0; kt < nk; kt++) {
        if (kt + 1 < nk) {
            uint32_t sb = sbase + ((kt + 1) & 1) * 61440;
            long long adv = (long long)(kt + 1) * 32;
            #pragma unroll
            for (int i = 0; i < 2; i++) {
                cp16(sb + aD[i], aS[i] + adv);
                cp16(sb + 10240 + aD[i], alS[i] + adv);
            }
            #pragma unroll
            for (int i = 0; i < 4; i++) {
                cp16(sb + 20480 + bD[i], bS[i] + adv);
                cp16(sb + 40960 + bD[i], blS[i] + adv);
            }
        }
        cp_commit();
        cp_wait1();
        __syncthreads();

        uint32_t sb = sbase + (kt & 1) * 61440;
        #pragma unroll
        for (int kk = 0; kk < 2; kk++) {
            uint32_t sa = sb + awarp + kk * 32 + aoff;
            uint32_t ah[2][4], al[2][4];
            ldm_x4(ah[0], sa);
            ldm_x4(ah[1], sa + 1280);
            ldm_x4(al[0], sa + 10240);
            ldm_x4(al[1], sa + 10240 + 1280);
            uint32_t sB0 = sb + 20480 + bwarp + kk * 32 + boff;
            #pragma unroll
            for (int g = 0; g < 8; g++) {
                uint32_t bh[4], bl[4];
                ldm_x4(bh, sB0 + g * 1280);
                ldm_x4(bl, sB0 + 20480 + g * 1280);
                #pragma unroll
                for (int mt = 0; mt < 2; mt++) {
                    mma16816(acc[mt][2 * g],     ah[mt], &bh[0]);
                    mma16816(acc[mt][2 * g + 1], ah[mt], &bh[2]);
                    mma16816(acc[mt][2 * g],     al[mt], &bh[0]);
                    mma16816(acc[mt][2 * g + 1], al[mt], &bh[2]);
                    mma16816(acc[mt][2 * g],     ah[mt], &bl[0]);
                    mma16816(acc[mt][2 * g + 1], ah[mt], &bl[2]);
                }
            }
        }
        __syncthreads();
    }

    // -------- stage accumulators to SMEM --------
    float* Ct = (float*)dsm;
    #pragma unroll
    for (int mt = 0; mt < 2; mt++)
        #pragma unroll
        for (int nt = 0; nt < 16; nt++) {
            int r = wm * 32 + mt * 16 + (lane >> 2);
            int c = wn * 128 + nt * 8 + (lane & 3) * 2;
            Ct[r * CT_STRIDE + c]           = acc[mt][nt][0];
            Ct[r * CT_STRIDE + c + 1]       = acc[mt][nt][1];
            Ct[(r + 8) * CT_STRIDE + c]     = acc[mt][nt][2];
            Ct[(r + 8) * CT_STRIDE + c + 1] = acc[mt][nt][3];
        }
    __syncthreads();

    // -------- fused bias + residual + LN (+relu) + write + bf16 emit --------
    // Each warp handles 16 rows; lane owns cols lane*8..lane*8+7 (fixed per row).
    float gg[8], bb[8], bs[8];
    *(float4*)gg       = *(const float4*)&lng[lane * 8];
    *(float4*)(gg + 4) = *(const float4*)&lng[lane * 8 + 4];
    *(float4*)bb       = *(const float4*)&lnb[lane * 8];
    *(float4*)(bb + 4) = *(const float4*)&lnb[lane * 8 + 4];
    *(float4*)bs       = *(const float4*)&biasS[lane * 8];
    *(float4*)(bs + 4) = *(const float4*)&biasS[lane * 8 + 4];

    for (int rr = 0; rr < 16; rr++) {
        int row = wid * 16 + rr;
        int grow = row0 + row;
        if (grow >= M) continue;
        const float* src = &Ct[row * CT_STRIDE + lane * 8];
        float x[8];
        *(float4*)x       = *(const float4*)src;
        *(float4*)(x + 4) = *(const float4*)(src + 4);
        float* hrow = &H[(long long)grow * 256 + lane * 8];
        if (RESID) {
            float4 h0 = *(const float4*)hrow, h1 = *(const float4*)(hrow + 4);
            x[0] = 0.5f * (x[0] + bs[0] + h0.x); x[1] = 0.5f * (x[1] + bs[1] + h0.y);
            x[2] = 0.5f * (x[2] + bs[2] + h0.z); x[3] = 0.5f * (x[3] + bs[3] + h0.w);
            x[4] = 0.5f * (x[4] + bs[4] + h1.x); x[5] = 0.5f * (x[5] + bs[5] + h1.y);
            x[6] = 0.5f * (x[6] + bs[6] + h1.z); x[7] = 0.5f * (x[7] + bs[7] + h1.w);
        } else {
            #pragma unroll
            for (int j = 0; j < 8; j++) x[j] += bs[j];
        }
        float s = 0.f, s2 = 0.f;
        #pragma unroll
        for (int j = 0; j < 8; j++) { s += x[j]; s2 += x[j] * x[j]; }
        #pragma unroll
        for (int o = 16; o > 0; o >>= 1) {
            s  += __shfl_xor_sync(0xffffffffu, s, o);
            s2 += __shfl_xor_sync(0xffffffffu, s2, o);
        }
        float mu = s * (1.f / 256.f);
        float var = s2 * (1.f / 256.f) - mu * mu;
        float rstd = rsqrtf(var + 1e-5f);
        float y[8];
        #pragma unroll
        for (int j = 0; j < 8; j++) {
            y[j] = gg[j] * (x[j] - mu) * rstd + bb[j];
            if (!RESID) y[j] = fmaxf(y[j], 0.f);
        }
        *(float4*)hrow       = *(const float4*)y;
        *(float4*)(hrow + 4) = *(const float4*)(y + 4);
        if (EMIT) {
            float lo[8];
            #pragma unroll
            for (int j = 0; j < 8; j++)
                lo[j] = y[j] - __bfloat162float(__float2bfloat16(y[j]));
            uint4 Hh, Ll;
            pack8_bf16(y, Hh);
            pack8_bf16(lo, Ll);
            *(uint4*)&Ohi[(long long)grow * 256 + lane * 8] = Hh;
            *(uint4*)&Olo[(long long)grow * 256 + lane * 8] = Ll;
        }
    }
}

// ---------------- conversions ----------------
__global__ void conv_x(const float4* __restrict__ src, long long n4,
                       __nv_bfloat16* __restrict__ hi, __nv_bfloat16* __restrict__ lo)
{
    for (long long i = blockIdx.x * (long long)blockDim.x + threadIdx.x; i < n4;
         i += (long long)gridDim.x * blockDim.x) {
        float4 v = src[i];
        float vv[4] = {v.x, v.y, v.z, v.w};
        uint32_t hp[2], lp[2];
        #pragma unroll
        for (int p = 0; p < 2; p++) {
            __nv_bfloat16 a = __float2bfloat16(vv[2 * p]);
            __nv_bfloat16 b = __float2bfloat16(vv[2 * p + 1]);
            __nv_bfloat16 c = __float2bfloat16(vv[2 * p] - __bfloat162float(a));
            __nv_bfloat16 d = __float2bfloat16(vv[2 * p + 1] - __bfloat162float(b));
            hp[p] = (uint32_t)__bfloat16_as_ushort(a) | ((uint32_t)__bfloat16_as_ushort(b) << 16);
            lp[p] = (uint32_t)__bfloat16_as_ushort(c) | ((uint32_t)__bfloat16_as_ushort(d) << 16);
        }
        *(uint2*)&hi[i * 4] = make_uint2(hp[0], hp[1]);
        *(uint2*)&lo[i * 4] = make_uint2(lp[0], lp[1]);
    }
}

// W [K,256] -> B [n][k] transposed hi/lo. grid = K blocks, 256 threads.
__global__ void convW(const float* __restrict__ W,
                      __nv_bfloat16* __restrict__ bhi, __nv_bfloat16* __restrict__ blo, int K)
{
    int k = blockIdx.x, n = threadIdx.x;
    float v = W[k * 256 + n];
    __nv_bfloat16 h = __float2bfloat16(v);
    bhi[n * K + k] = h;
    blo[n * K + k] = __float2bfloat16(v - __bfloat162float(h));
}

// out = h @ W_out + b_out : [M,256] x [256,40]
__global__ void __launch_bounds__(256) out_gemm(
    const float* __restrict__ h, const float* __restrict__ W,
    const float* __restrict__ bias, float* __restrict__ out, int M)
{
    __shared__ float hs[64][65];
    __shared__ float Ws[64][40];
    const int r0 = blockIdx.x * 64;
    const int tid = threadIdx.x;
    const int r = tid & 63, cg = tid >> 6;
    float acc[10];
    #pragma unroll
    for (int j = 0; j < 10; j++) acc[j] = 0.f;

    for (int k0 = 0; k0 < 256; k0 += 64) {
        #pragma unroll
        for (int s = 0; s < 4; s++) {
            int l = tid + s * 256;
            int hr = l >> 4, hk = (l & 15) * 4;
            float4 hv = make_float4(0.f, 0.f, 0.f, 0.f);
            int gr = r0 + hr;
            if (gr < M) hv = *(const float4*)&h[(long long)gr * 256 + k0 + hk];
            hs[hr][hk] = hv.x; hs[hr][hk + 1] = hv.y; hs[hr][hk + 2] = hv.z; hs[hr][hk + 3] = hv.w;
        }
        #pragma unroll
        for (int s = 0; s < 10; s++) {
            int l = tid + s * 256;
            int wk = l / 40, wc = l % 40;
            Ws[wk][wc] = W[(k0 + wk) * 40 + wc];
        }
        __syncthreads();
        #pragma unroll
        for (int k = 0; k < 64; k++) {
            float a = hs[r][k];
            #pragma unroll
            for (int j = 0; j < 10; j++) acc[j] += a * Ws[k][cg * 10 + j];
        }
        __syncthreads();
    }
    int gr = r0 + r;
    if (gr < M) {
        #pragma unroll
        for (int j = 0; j < 10; j++)
            out[(long long)gr * 40 + cg * 10 + j] = acc[j] + bias[cg * 10 + j];
    }
}

// ---------------- launch ----------------
extern "C" void kernel_launch(void* const* d_in, const int* in_sizes, int n_in,
                              void* d_out, int out_size)
{
    const float* x     = (const float*)d_in[0];
    const float* W_in  = (const float*)d_in[2];
    const float* b_in  = (const float*)d_in[3];
    const float* ln0g  = (const float*)d_in[4];
    const float* ln0b  = (const float*)d_in[5];
    const float* Wv[2] = {(const float*)d_in[10], (const float*)d_in[18]};
    const float* bv[2] = {(const float*)d_in[11], (const float*)d_in[19]};
    const float* lng[2] = {(const float*)d_in[12], (const float*)d_in[20]};
    const float* lnb[2] = {(const float*)d_in[13], (const float*)d_in[21]};
    const float* W_out = (const float*)d_in[22];
    const float* b_out = (const float*)d_in[23];
    float* out = (float*)d_out;

    const int M = in_sizes[0] / 512;
    const int tiles = (M + 127) / 128;

    float *ph;
    __nv_bfloat16 *pAhi, *pAlo, *pHhi, *pHlo, *pBhi, *pBlo;
    cudaGetSymbolAddress((void**)&ph,   g_h);
    cudaGetSymbolAddress((void**)&pAhi, g_Ahi);
    cudaGetSymbolAddress((void**)&pAlo, g_Alo);
    cudaGetSymbolAddress((void**)&pHhi, g_Hhi);
    cudaGetSymbolAddress((void**)&pHlo, g_Hlo);
    cudaGetSymbolAddress((void**)&pBhi, g_Bhi);
    cudaGetSymbolAddress((void**)&pBlo, g_Blo);

    cudaFuncSetAttribute(gemm_fused<0, 1>, cudaFuncAttributeMaxDynamicSharedMemorySize, DSMEM);
    cudaFuncSetAttribute(gemm_fused<1, 1>, cudaFuncAttributeMaxDynamicSharedMemorySize, DSMEM);
    cudaFuncSetAttribute(gemm_fused<1, 0>, cudaFuncAttributeMaxDynamicSharedMemorySize, DSMEM);

    // x -> bf16 hi/lo; W_in -> [256][512] transposed hi/lo
    conv_x<<<2048, 256>>>((const float4*)x, (long long)M * 512 / 4, pAhi, pAlo);
    convW<<<512, 256>>>(W_in, pBhi, pBlo, 512);
    // h = relu(LN(x @ W_in + b_in)); emit h bf16 hi/lo
    gemm_fused<0, 1><<<tiles, 256, DSMEM>>>(pAhi, pAlo, 512, pBhi, pBlo, b_in,
                                            ph, pHhi, pHlo, ln0g, ln0b, M, 512);

    for (int l = 0; l < 2; l++) {
        convW<<<256, 256>>>(Wv[l], pBhi, pBlo, 256);
        // h = LN(0.5*(h@Wv+bv) + 0.5*h); l=0 re-emits bf16 h in place (race-free: own rows)
        if (l == 0)
            gemm_fused<1, 1><<<tiles, 256, DSMEM>>>(pHhi, pHlo, 256, pBhi, pBlo, bv[l],
                                                    ph, pHhi, pHlo, lng[l], lnb[l], M, 256);
        else
            gemm_fused<1, 0><<<tiles, 256, DSMEM>>>(pHhi, pHlo, 256, pBhi, pBlo, bv[l],
                                                    ph, nullptr, nullptr, lng[l], lnb[l], M, 256);
    }

    // out = h @ W_out + b_out
    out_gemm<<<(M + 63) / 64, 256>>>(ph, W_out, b_out, out, M);
}

// round 9
// speedup vs baseline: 1.1284x; 1.1284x over previous
#include <cuda_runtime.h>
#include <cuda_bf16.h>
#include <cstdint>

#define MAXN 100000

// ---------------- device scratch ----------------
__device__ float g_h[MAXN * 256];            // hidden state fp32
__device__ __nv_bfloat16 g_Ahi[MAXN * 512];  // x hi (bf16), lda=512
__device__ __nv_bfloat16 g_Alo[MAXN * 512];  // x lo
__device__ __nv_bfloat16 g_Hhi[MAXN * 256];  // h hi (bf16), lda=256
__device__ __nv_bfloat16 g_Hlo[MAXN * 256];  // h lo
__device__ __nv_bfloat16 g_Bhi[256 * 512];   // weight operand hi, [n][k]
__device__ __nv_bfloat16 g_Blo[256 * 512];   // weight operand lo

// ---------------- PTX helpers (compute_103-safe) ----------------
__device__ __forceinline__ uint32_t smem_u32(const void* p) {
    uint32_t a;
    asm("{ .reg .u64 t; cvta.to.shared.u64 t, %1; cvt.u32.u64 %0, t; }" : "=r"(a) : "l"(p));
    return a;
}
__device__ __forceinline__ void cp16(uint32_t dst, const void* src) {
    asm volatile("cp.async.cg.shared.global [%0], [%1], 16;" :: "r"(dst), "l"(src));
}
__device__ __forceinline__ void cp_commit() {
    asm volatile("cp.async.commit_group;" ::: "memory");
}
__device__ __forceinline__ void cp_wait1() {
    asm volatile("cp.async.wait_group 1;" ::: "memory");
}
__device__ __forceinline__ void ldm_x4(uint32_t* r, uint32_t addr) {
    asm volatile("ldmatrix.sync.aligned.m8n8.x4.shared.b16 {%0,%1,%2,%3}, [%4];"
        : "=r"(r[0]), "=r"(r[1]), "=r"(r[2]), "=r"(r[3]) : "r"(addr));
}
__device__ __forceinline__ void mma16816(float* c, const uint32_t* a, const uint32_t* b) {
    asm volatile("mma.sync.aligned.m16n8k16.row.col.f32.bf16.bf16.f32 "
        "{%0,%1,%2,%3}, {%4,%5,%6,%7}, {%8,%9}, {%0,%1,%2,%3};"
        : "+f"(c[0]), "+f"(c[1]), "+f"(c[2]), "+f"(c[3])
        : "r"(a[0]), "r"(a[1]), "r"(a[2]), "r"(a[3]), "r"(b[0]), "r"(b[1]));
}

// SMEM per stage (80B row stride): AH @0 (10240), AL @10240, BH @20480 (20480), BL @40960
// Stage = 61440, three stages = 184320.
#define STAGE 61440
#define DSMEM 184320

// ============ fused GEMM + LN: one CTA owns a full 128-row x 256-col output ============
// C = (Ahi+Alo)[M,K] @ (Bhi+Blo)[256,K]^T + bias, then:
//   RESID=0: h = relu(LN(C));  RESID=1: h = LN(0.5*C + 0.5*h)
// EMIT=1: also write bf16 hi/lo of h into Ohi/Olo (same rows CTA read -> race-free).
// grid = ceil(M/128), 512 threads (16 warps: 4m x 4n, 32x64 warp tile).
template<int RESID, int EMIT>
__global__ void __launch_bounds__(512, 1) gemm_fused(
    const __nv_bfloat16* __restrict__ Ahi, const __nv_bfloat16* __restrict__ Alo, int lda,
    const __nv_bfloat16* __restrict__ Bhi, const __nv_bfloat16* __restrict__ Blo,
    const float* __restrict__ bias,
    float* __restrict__ H,
    __nv_bfloat16* __restrict__ Ohi, __nv_bfloat16* __restrict__ Olo,
    const float* __restrict__ lng, const float* __restrict__ lnb,
    int M, int K)
{
    extern __shared__ char dsm[];
    __shared__ float2 red[128][4];
    const int tid = threadIdx.x;
    const int lane = tid & 31, wid = tid >> 5;
    const int wm = wid >> 2, wn = wid & 3;        // 4 x 4 warp grid
    const int row0 = blockIdx.x * 128;
    const int nk = K >> 5;                         // BK=32

    const uint32_t sbase = smem_u32(dsm);

    // cp.async: 6 x 16B chunks/thread/stage (A hi/lo: 512 each, B hi/lo: 1024 each)
    const __nv_bfloat16* gP[6];
    uint32_t sO[6];
    #pragma unroll
    for (int i = 0; i < 6; i++) {
        int cid = tid + i * 512;
        if (cid < 512) {                 // A hi
            int r = cid >> 2, seg = cid & 3;
            int ar = min(row0 + r, M - 1);
            gP[i] = Ahi + (long long)ar * lda + seg * 8;
            sO[i] = (uint32_t)(r * 80 + seg * 16);
        } else if (cid < 1024) {         // A lo
            int c2 = cid - 512;
            int r = c2 >> 2, seg = c2 & 3;
            int ar = min(row0 + r, M - 1);
            gP[i] = Alo + (long long)ar * lda + seg * 8;
            sO[i] = 10240u + (uint32_t)(r * 80 + seg * 16);
        } else if (cid < 2048) {         // B hi
            int c2 = cid - 1024;
            int r = c2 >> 2, seg = c2 & 3;
            gP[i] = Bhi + (long long)r * K + seg * 8;
            sO[i] = 20480u + (uint32_t)(r * 80 + seg * 16);
        } else {                         // B lo
            int c2 = cid - 2048;
            int r = c2 >> 2, seg = c2 & 3;
            gP[i] = Blo + (long long)r * K + seg * 8;
            sO[i] = 40960u + (uint32_t)(r * 80 + seg * 16);
        }
    }

    auto issue = [&](int kt) {
        uint32_t sb = sbase + (uint32_t)(kt % 3) * STAGE;
        long long adv = (long long)kt * 32;
        #pragma unroll
        for (int i = 0; i < 6; i++) cp16(sb + sO[i], gP[i] + adv);
        cp_commit();
    };

    float acc[2][8][4] = {};

    issue(0);
    issue(1);

    const uint32_t aoff = (uint32_t)((lane & 15) * 80 + (lane >> 4) * 16);
    const uint32_t boff = (uint32_t)(((lane & 7) + ((lane >> 4) << 3)) * 80 + (((lane >> 3) & 1) << 4));
    const uint32_t awarp = (uint32_t)(wm * 32) * 80;
    const uint32_t bwarp = (uint32_t)(wn * 64) * 80;

    int buf = 0;
    for (int kt = 0; kt < nk; kt++) {
        cp_wait1();
        __syncthreads();

        uint32_t sb = sbase + (uint32_t)buf * STAGE;
        #pragma unroll
        for (int kk = 0; kk < 2; kk++) {
            uint32_t sa = sb + awarp + kk * 32 + aoff;
            uint32_t ah[2][4], al[2][4];
            ldm_x4(ah[0], sa);
            ldm_x4(ah[1], sa + 1280);
            ldm_x4(al[0], sa + 10240);
            ldm_x4(al[1], sa + 10240 + 1280);
            uint32_t sB0 = sb + 20480 + bwarp + kk * 32 + boff;
            #pragma unroll
            for (int g = 0; g < 4; g++) {
                uint32_t bh[4], bl[4];
                ldm_x4(bh, sB0 + g * 1280);
                ldm_x4(bl, sB0 + 20480 + g * 1280);
                #pragma unroll
                for (int mt = 0; mt < 2; mt++) {
                    mma16816(acc[mt][2 * g],     ah[mt], &bh[0]);
                    mma16816(acc[mt][2 * g + 1], ah[mt], &bh[2]);
                    mma16816(acc[mt][2 * g],     al[mt], &bh[0]);
                    mma16816(acc[mt][2 * g + 1], al[mt], &bh[2]);
                    mma16816(acc[mt][2 * g],     ah[mt], &bl[0]);
                    mma16816(acc[mt][2 * g + 1], ah[mt], &bl[2]);
                }
            }
        }
        // issue into stage (kt+2)%3: all warps passed this iteration's barrier,
        // so stage (kt-1)%3 == (kt+2)%3 is fully consumed.
        if (kt + 2 < nk) issue(kt + 2);
        buf = (buf == 2) ? 0 : buf + 1;
    }

    // -------- fragment-direct epilogue: bias + residual + LN (+relu) + stores --------
    // Thread owns rows: wm*32 + mt*16 + (lane>>2) + 8*hh ; cols: wn*64 + nt*8 + (lane&3)*2 {+0,1}
    const int cbase = wn * 64 + (lane & 3) * 2;
    float sA[2][2], s2A[2][2];
    #pragma unroll
    for (int mt = 0; mt < 2; mt++)
        #pragma unroll
        for (int hh = 0; hh < 2; hh++) {
            int row = wm * 32 + mt * 16 + (lane >> 2) + hh * 8;
            int gclamp = min(row0 + row, M - 1);
            float s = 0.f, s2 = 0.f;
            #pragma unroll
            for (int nt = 0; nt < 8; nt++) {
                int c = cbase + nt * 8;
                float2 bsv = *(const float2*)&bias[c];
                float x0 = acc[mt][nt][2 * hh], x1 = acc[mt][nt][2 * hh + 1];
                if (RESID) {
                    float2 hv = *(const float2*)&H[(long long)gclamp * 256 + c];
                    x0 = 0.5f * (x0 + bsv.x + hv.x);
                    x1 = 0.5f * (x1 + bsv.y + hv.y);
                } else {
                    x0 += bsv.x; x1 += bsv.y;
                }
                acc[mt][nt][2 * hh] = x0;
                acc[mt][nt][2 * hh + 1] = x1;
                s += x0 + x1;
                s2 += x0 * x0 + x1 * x1;
            }
            s  += __shfl_xor_sync(0xffffffffu, s, 1);
            s  += __shfl_xor_sync(0xffffffffu, s, 2);
            s2 += __shfl_xor_sync(0xffffffffu, s2, 1);
            s2 += __shfl_xor_sync(0xffffffffu, s2, 2);
            sA[mt][hh] = s; s2A[mt][hh] = s2;
            if ((lane & 3) == 0) red[row][wn] = make_float2(s, s2);
        }
    __syncthreads();

    #pragma unroll
    for (int mt = 0; mt < 2; mt++)
        #pragma unroll
        for (int hh = 0; hh < 2; hh++) {
            int row = wm * 32 + mt * 16 + (lane >> 2) + hh * 8;
            int grow = row0 + row;
            float2 r0 = red[row][0], r1 = red[row][1], r2 = red[row][2], r3 = red[row][3];
            float s  = r0.x + r1.x + r2.x + r3.x;
            float s2 = r0.y + r1.y + r2.y + r3.y;
            float mu = s * (1.f / 256.f);
            float var = s2 * (1.f / 256.f) - mu * mu;
            float rstd = rsqrtf(var + 1e-5f);
            if (grow < M) {
                #pragma unroll
                for (int nt = 0; nt < 8; nt++) {
                    int c = cbase + nt * 8;
                    float2 gv = *(const float2*)&lng[c];
                    float2 bv = *(const float2*)&lnb[c];
                    float y0 = gv.x * (acc[mt][nt][2 * hh] - mu) * rstd + bv.x;
                    float y1 = gv.y * (acc[mt][nt][2 * hh + 1] - mu) * rstd + bv.y;
                    if (!RESID) { y0 = fmaxf(y0, 0.f); y1 = fmaxf(y1, 0.f); }
                    *(float2*)&H[(long long)grow * 256 + c] = make_float2(y0, y1);
                    if (EMIT) {
                        __nv_bfloat16 h0 = __float2bfloat16(y0);
                        __nv_bfloat16 h1 = __float2bfloat16(y1);
                        uint32_t hp = (uint32_t)__bfloat16_as_ushort(h0) |
                                      ((uint32_t)__bfloat16_as_ushort(h1) << 16);
                        float l0 = y0 - __bfloat162float(h0);
                        float l1 = y1 - __bfloat162float(h1);
                        uint32_t lp = (uint32_t)__bfloat16_as_ushort(__float2bfloat16(l0)) |
                                      ((uint32_t)__bfloat16_as_ushort(__float2bfloat16(l1)) << 16);
                        *(uint32_t*)&Ohi[(long long)grow * 256 + c] = hp;
                        *(uint32_t*)&Olo[(long long)grow * 256 + c] = lp;
                    }
                }
            }
        }
    (void)sA; (void)s2A;
}

// ---------------- conversions ----------------
__global__ void conv_x(const float4* __restrict__ src, long long n4,
                       __nv_bfloat16* __restrict__ hi, __nv_bfloat16* __restrict__ lo)
{
    for (long long i = blockIdx.x * (long long)blockDim.x + threadIdx.x; i < n4;
         i += (long long)gridDim.x * blockDim.x) {
        float4 v = src[i];
        float vv[4] = {v.x, v.y, v.z, v.w};
        uint32_t hp[2], lp[2];
        #pragma unroll
        for (int p = 0; p < 2; p++) {
            __nv_bfloat16 a = __float2bfloat16(vv[2 * p]);
            __nv_bfloat16 b = __float2bfloat16(vv[2 * p + 1]);
            __nv_bfloat16 c = __float2bfloat16(vv[2 * p] - __bfloat162float(a));
            __nv_bfloat16 d = __float2bfloat16(vv[2 * p + 1] - __bfloat162float(b));
            hp[p] = (uint32_t)__bfloat16_as_ushort(a) | ((uint32_t)__bfloat16_as_ushort(b) << 16);
            lp[p] = (uint32_t)__bfloat16_as_ushort(c) | ((uint32_t)__bfloat16_as_ushort(d) << 16);
        }
        *(uint2*)&hi[i * 4] = make_uint2(hp[0], hp[1]);
        *(uint2*)&lo[i * 4] = make_uint2(lp[0], lp[1]);
    }
}

// W [K,256] -> B [n][k] transposed hi/lo. grid = K blocks, 256 threads.
__global__ void convW(const float* __restrict__ W,
                      __nv_bfloat16* __restrict__ bhi, __nv_bfloat16* __restrict__ blo, int K)
{
    int k = blockIdx.x, n = threadIdx.x;
    float v = W[k * 256 + n];
    __nv_bfloat16 h = __float2bfloat16(v);
    bhi[n * K + k] = h;
    blo[n * K + k] = __float2bfloat16(v - __bfloat162float(h));
}

// out = h @ W_out + b_out : [M,256] x [256,40]
__global__ void __launch_bounds__(256) out_gemm(
    const float* __restrict__ h, const float* __restrict__ W,
    const float* __restrict__ bias, float* __restrict__ out, int M)
{
    __shared__ float hs[64][65];
    __shared__ float Ws[64][40];
    const int r0 = blockIdx.x * 64;
    const int tid = threadIdx.x;
    const int r = tid & 63, cg = tid >> 6;
    float acc[10];
    #pragma unroll
    for (int j = 0; j < 10; j++) acc[j] = 0.f;

    for (int k0 = 0; k0 < 256; k0 += 64) {
        #pragma unroll
        for (int s = 0; s < 4; s++) {
            int l = tid + s * 256;
            int hr = l >> 4, hk = (l & 15) * 4;
            float4 hv = make_float4(0.f, 0.f, 0.f, 0.f);
            int gr = r0 + hr;
            if (gr < M) hv = *(const float4*)&h[(long long)gr * 256 + k0 + hk];
            hs[hr][hk] = hv.x; hs[hr][hk + 1] = hv.y; hs[hr][hk + 2] = hv.z; hs[hr][hk + 3] = hv.w;
        }
        #pragma unroll
        for (int s = 0; s < 10; s++) {
            int l = tid + s * 256;
            int wk = l / 40, wc = l % 40;
            Ws[wk][wc] = W[(k0 + wk) * 40 + wc];
        }
        __syncthreads();
        #pragma unroll
        for (int k = 0; k < 64; k++) {
            float a = hs[r][k];
            #pragma unroll
            for (int j = 0; j < 10; j++) acc[j] += a * Ws[k][cg * 10 + j];
        }
        __syncthreads();
    }
    int gr = r0 + r;
    if (gr < M) {
        #pragma unroll
        for (int j = 0; j < 10; j++)
            out[(long long)gr * 40 + cg * 10 + j] = acc[j] + bias[cg * 10 + j];
    }
}

// ---------------- launch ----------------
extern "C" void kernel_launch(void* const* d_in, const int* in_sizes, int n_in,
                              void* d_out, int out_size)
{
    const float* x     = (const float*)d_in[0];
    const float* W_in  = (const float*)d_in[2];
    const float* b_in  = (const float*)d_in[3];
    const float* ln0g  = (const float*)d_in[4];
    const float* ln0b  = (const float*)d_in[5];
    const float* Wv[2] = {(const float*)d_in[10], (const float*)d_in[18]};
    const float* bv[2] = {(const float*)d_in[11], (const float*)d_in[19]};
    const float* lng[2] = {(const float*)d_in[12], (const float*)d_in[20]};
    const float* lnb[2] = {(const float*)d_in[13], (const float*)d_in[21]};
    const float* W_out = (const float*)d_in[22];
    const float* b_out = (const float*)d_in[23];
    float* out = (float*)d_out;

    const int M = in_sizes[0] / 512;
    const int tiles = (M + 127) / 128;

    float *ph;
    __nv_bfloat16 *pAhi, *pAlo, *pHhi, *pHlo, *pBhi, *pBlo;
    cudaGetSymbolAddress((void**)&ph,   g_h);
    cudaGetSymbolAddress((void**)&pAhi, g_Ahi);
    cudaGetSymbolAddress((void**)&pAlo, g_Alo);
    cudaGetSymbolAddress((void**)&pHhi, g_Hhi);
    cudaGetSymbolAddress((void**)&pHlo, g_Hlo);
    cudaGetSymbolAddress((void**)&pBhi, g_Bhi);
    cudaGetSymbolAddress((void**)&pBlo, g_Blo);

    cudaFuncSetAttribute(gemm_fused<0, 1>, cudaFuncAttributeMaxDynamicSharedMemorySize, DSMEM);
    cudaFuncSetAttribute(gemm_fused<1, 1>, cudaFuncAttributeMaxDynamicSharedMemorySize, DSMEM);
    cudaFuncSetAttribute(gemm_fused<1, 0>, cudaFuncAttributeMaxDynamicSharedMemorySize, DSMEM);

    // x -> bf16 hi/lo; W_in -> [256][512] transposed hi/lo
    conv_x<<<2048, 256>>>((const float4*)x, (long long)M * 512 / 4, pAhi, pAlo);
    convW<<<512, 256>>>(W_in, pBhi, pBlo, 512);
    // h = relu(LN(x @ W_in + b_in)); emit h bf16 hi/lo
    gemm_fused<0, 1><<<tiles, 512, DSMEM>>>(pAhi, pAlo, 512, pBhi, pBlo, b_in,
                                            ph, pHhi, pHlo, ln0g, ln0b, M, 512);

    for (int l = 0; l < 2; l++) {
        convW<<<256, 256>>>(Wv[l], pBhi, pBlo, 256);
        // h = LN(0.5*(h@Wv+bv) + 0.5*h); l=0 re-emits bf16 h in place (race-free: own rows)
        if (l == 0)
            gemm_fused<1, 1><<<tiles, 512, DSMEM>>>(pHhi, pHlo, 256, pBhi, pBlo, bv[l],
                                                    ph, pHhi, pHlo, lng[l], lnb[l], M, 256);
        else
            gemm_fused<1, 0><<<tiles, 512, DSMEM>>>(pHhi, pHlo, 256, pBhi, pBlo, bv[l],
                                                    ph, nullptr, nullptr, lng[l], lnb[l], M, 256);
    }

    // out = h @ W_out + b_out
    out_gemm<<<(M + 63) / 64, 256>>>(ph, W_out, b_out, out, M);
}

// round 10
// speedup vs baseline: 1.4562x; 1.2904x over previous
#include <cuda_runtime.h>
#include <cuda_fp16.h>
#include <cstdint>

#define MAXN 100000

// ---------------- device scratch ----------------
__device__ float g_h[MAXN * 256];          // hidden state fp32
__device__ __half g_A[MAXN * 512];         // x fp16 (single), lda=512
__device__ __half g_H[MAXN * 256];         // h fp16 (single), lda=256
__device__ __half g_Bhi[256 * 512];        // weight hi, [n][k]
__device__ __half g_Blo[256 * 512];        // weight lo

// ---------------- PTX helpers (compute_103-safe) ----------------
__device__ __forceinline__ uint32_t smem_u32(const void* p) {
    uint32_t a;
    asm("{ .reg .u64 t; cvta.to.shared.u64 t, %1; cvt.u32.u64 %0, t; }" : "=r"(a) : "l"(p));
    return a;
}
__device__ __forceinline__ void cp16(uint32_t dst, const void* src) {
    asm volatile("cp.async.cg.shared.global [%0], [%1], 16;" :: "r"(dst), "l"(src));
}
__device__ __forceinline__ void cp_commit() {
    asm volatile("cp.async.commit_group;" ::: "memory");
}
__device__ __forceinline__ void cp_wait1() {
    asm volatile("cp.async.wait_group 1;" ::: "memory");
}
__device__ __forceinline__ void ldm_x4(uint32_t* r, uint32_t addr) {
    asm volatile("ldmatrix.sync.aligned.m8n8.x4.shared.b16 {%0,%1,%2,%3}, [%4];"
        : "=r"(r[0]), "=r"(r[1]), "=r"(r[2]), "=r"(r[3]) : "r"(addr));
}
__device__ __forceinline__ void mma16816(float* c, const uint32_t* a, const uint32_t* b) {
    asm volatile("mma.sync.aligned.m16n8k16.row.col.f32.f16.f16.f32 "
        "{%0,%1,%2,%3}, {%4,%5,%6,%7}, {%8,%9}, {%0,%1,%2,%3};"
        : "+f"(c[0]), "+f"(c[1]), "+f"(c[2]), "+f"(c[3])
        : "r"(a[0]), "r"(a[1]), "r"(a[2]), "r"(a[3]), "r"(b[0]), "r"(b[1]));
}

// SMEM per stage (80B row stride): A @0 (10240), BH @10240 (20480), BL @30720 (20480)
// Stage = 51200, three stages = 153600.
#define STAGE 51200
#define DSMEM 153600

// ============ fused GEMM + LN: one CTA owns a full 128-row x 256-col output ============
// C = A[M,K] @ (Bhi+Blo)[256,K]^T + bias  (A single fp16, B split fp16: 2 products), then:
//   RESID=0: h = relu(LN(C));  RESID=1: h = LN(0.5*C + 0.5*h)
// EMIT=1: also write fp16 of h into Oh (same rows this CTA read -> race-free).
// grid = ceil(M/128), 512 threads (16 warps: 4m x 4n, 32x64 warp tile).
template<int RESID, int EMIT>
__global__ void __launch_bounds__(512, 1) gemm_fused(
    const __half* __restrict__ A, int lda,
    const __half* __restrict__ Bhi, const __half* __restrict__ Blo,
    const float* __restrict__ bias,
    float* __restrict__ H,
    __half* __restrict__ Oh,
    const float* __restrict__ lng, const float* __restrict__ lnb,
    int M, int K)
{
    extern __shared__ char dsm[];
    __shared__ float2 red[128][4];
    const int tid = threadIdx.x;
    const int lane = tid & 31, wid = tid >> 5;
    const int wm = wid >> 2, wn = wid & 3;        // 4 x 4 warp grid
    const int row0 = blockIdx.x * 128;
    const int nk = K >> 5;                         // BK=32

    const uint32_t sbase = smem_u32(dsm);

    // cp.async: 5 x 16B chunks/thread/stage (A: 512, B hi: 1024, B lo: 1024)
    const __half* gP[5];
    uint32_t sO[5];
    #pragma unroll
    for (int i = 0; i < 5; i++) {
        int cid = tid + i * 512;
        if (cid < 512) {                 // A
            int r = cid >> 2, seg = cid & 3;
            int ar = min(row0 + r, M - 1);
            gP[i] = A + (long long)ar * lda + seg * 8;
            sO[i] = (uint32_t)(r * 80 + seg * 16);
        } else if (cid < 1536) {         // B hi
            int c2 = cid - 512;
            int r = c2 >> 2, seg = c2 & 3;
            gP[i] = Bhi + (long long)r * K + seg * 8;
            sO[i] = 10240u + (uint32_t)(r * 80 + seg * 16);
        } else {                         // B lo
            int c2 = cid - 1536;
            int r = c2 >> 2, seg = c2 & 3;
            gP[i] = Blo + (long long)r * K + seg * 8;
            sO[i] = 30720u + (uint32_t)(r * 80 + seg * 16);
        }
    }

    auto issue = [&](int kt) {
        uint32_t sb = sbase + (uint32_t)(kt % 3) * STAGE;
        long long adv = (long long)kt * 32;
        #pragma unroll
        for (int i = 0; i < 5; i++) cp16(sb + sO[i], gP[i] + adv);
        cp_commit();
    };

    float acc[2][8][4] = {};

    issue(0);
    issue(1);

    const uint32_t aoff = (uint32_t)((lane & 15) * 80 + (lane >> 4) * 16);
    const uint32_t boff = (uint32_t)(((lane & 7) + ((lane >> 4) << 3)) * 80 + (((lane >> 3) & 1) << 4));
    const uint32_t awarp = (uint32_t)(wm * 32) * 80;
    const uint32_t bwarp = (uint32_t)(wn * 64) * 80;

    int buf = 0;
    for (int kt = 0; kt < nk; kt++) {
        cp_wait1();
        __syncthreads();

        uint32_t sb = sbase + (uint32_t)buf * STAGE;
        #pragma unroll
        for (int kk = 0; kk < 2; kk++) {
            uint32_t sa = sb + awarp + kk * 32 + aoff;
            uint32_t ah[2][4];
            ldm_x4(ah[0], sa);
            ldm_x4(ah[1], sa + 1280);
            uint32_t sB0 = sb + 10240 + bwarp + kk * 32 + boff;
            #pragma unroll
            for (int g = 0; g < 4; g++) {
                uint32_t bh[4], bl[4];
                ldm_x4(bh, sB0 + g * 1280);
                ldm_x4(bl, sB0 + 20480 + g * 1280);
                #pragma unroll
                for (int mt = 0; mt < 2; mt++) {
                    mma16816(acc[mt][2 * g],     ah[mt], &bh[0]);
                    mma16816(acc[mt][2 * g + 1], ah[mt], &bh[2]);
                    mma16816(acc[mt][2 * g],     ah[mt], &bl[0]);
                    mma16816(acc[mt][2 * g + 1], ah[mt], &bl[2]);
                }
            }
        }
        // issue into stage (kt+2)%3: all warps passed this iteration's barrier,
        // so stage (kt-1)%3 == (kt+2)%3 is fully consumed.
        if (kt + 2 < nk) issue(kt + 2);
        buf = (buf == 2) ? 0 : buf + 1;
    }

    // -------- fragment-direct epilogue: bias + residual + LN (+relu) + stores --------
    // Thread owns rows: wm*32 + mt*16 + (lane>>2) + 8*hh ; cols: wn*64 + nt*8 + (lane&3)*2 {+0,1}
    const int cbase = wn * 64 + (lane & 3) * 2;
    #pragma unroll
    for (int mt = 0; mt < 2; mt++)
        #pragma unroll
        for (int hh = 0; hh < 2; hh++) {
            int row = wm * 32 + mt * 16 + (lane >> 2) + hh * 8;
            int gclamp = min(row0 + row, M - 1);
            float s = 0.f, s2 = 0.f;
            #pragma unroll
            for (int nt = 0; nt < 8; nt++) {
                int c = cbase + nt * 8;
                float2 bsv = *(const float2*)&bias[c];
                float x0 = acc[mt][nt][2 * hh], x1 = acc[mt][nt][2 * hh + 1];
                if (RESID) {
                    float2 hv = *(const float2*)&H[(long long)gclamp * 256 + c];
                    x0 = 0.5f * (x0 + bsv.x + hv.x);
                    x1 = 0.5f * (x1 + bsv.y + hv.y);
                } else {
                    x0 += bsv.x; x1 += bsv.y;
                }
                acc[mt][nt][2 * hh] = x0;
                acc[mt][nt][2 * hh + 1] = x1;
                s += x0 + x1;
                s2 += x0 * x0 + x1 * x1;
            }
            s  += __shfl_xor_sync(0xffffffffu, s, 1);
            s  += __shfl_xor_sync(0xffffffffu, s, 2);
            s2 += __shfl_xor_sync(0xffffffffu, s2, 1);
            s2 += __shfl_xor_sync(0xffffffffu, s2, 2);
            if ((lane & 3) == 0) red[row][wn] = make_float2(s, s2);
        }
    __syncthreads();

    #pragma unroll
    for (int mt = 0; mt < 2; mt++)
        #pragma unroll
        for (int hh = 0; hh < 2; hh++) {
            int row = wm * 32 + mt * 16 + (lane >> 2) + hh * 8;
            int grow = row0 + row;
            float2 r0 = red[row][0], r1 = red[row][1], r2 = red[row][2], r3 = red[row][3];
            float s  = r0.x + r1.x + r2.x + r3.x;
            float s2 = r0.y + r1.y + r2.y + r3.y;
            float mu = s * (1.f / 256.f);
            float var = s2 * (1.f / 256.f) - mu * mu;
            float rstd = rsqrtf(var + 1e-5f);
            if (grow < M) {
                #pragma unroll
                for (int nt = 0; nt < 8; nt++) {
                    int c = cbase + nt * 8;
                    float2 gv = *(const float2*)&lng[c];
                    float2 bv = *(const float2*)&lnb[c];
                    float y0 = gv.x * (acc[mt][nt][2 * hh] - mu) * rstd + bv.x;
                    float y1 = gv.y * (acc[mt][nt][2 * hh + 1] - mu) * rstd + bv.y;
                    if (!RESID) { y0 = fmaxf(y0, 0.f); y1 = fmaxf(y1, 0.f); }
                    *(float2*)&H[(long long)grow * 256 + c] = make_float2(y0, y1);
                    if (EMIT) {
                        __half h0 = __float2half(y0);
                        __half h1 = __float2half(y1);
                        uint32_t hp = (uint32_t)__half_as_ushort(h0) |
                                      ((uint32_t)__half_as_ushort(h1) << 16);
                        *(uint32_t*)&Oh[(long long)grow * 256 + c] = hp;
                    }
                }
            }
        }
}

// ---------------- conversions ----------------
// x fp32 -> fp16 (single)
__global__ void conv_x(const float4* __restrict__ src, long long n4,
                       __half* __restrict__ dst)
{
    for (long long i = blockIdx.x * (long long)blockDim.x + threadIdx.x; i < n4;
         i += (long long)gridDim.x * blockDim.x) {
        float4 v = src[i];
        __half2 p0 = __floats2half2_rn(v.x, v.y);
        __half2 p1 = __floats2half2_rn(v.z, v.w);
        uint32_t w0, w1;
        w0 = *(uint32_t*)&p0;
        w1 = *(uint32_t*)&p1;
        *(uint2*)&dst[i * 4] = make_uint2(w0, w1);
    }
}

// W [K,256] -> B [n][k] transposed fp16 hi/lo. grid = K blocks, 256 threads.
__global__ void convW(const float* __restrict__ W,
                      __half* __restrict__ bhi, __half* __restrict__ blo, int K)
{
    int k = blockIdx.x, n = threadIdx.x;
    float v = W[k * 256 + n];
    __half h = __float2half(v);
    bhi[n * K + k] = h;
    blo[n * K + k] = __float2half(v - __half2float(h));
}

// out = h @ W_out + b_out : [M,256] x [256,40]  (fp32 SIMT)
__global__ void __launch_bounds__(256) out_gemm(
    const float* __restrict__ h, const float* __restrict__ W,
    const float* __restrict__ bias, float* __restrict__ out, int M)
{
    __shared__ float hs[64][65];
    __shared__ float Ws[64][40];
    const int r0 = blockIdx.x * 64;
    const int tid = threadIdx.x;
    const int r = tid & 63, cg = tid >> 6;
    float acc[10];
    #pragma unroll
    for (int j = 0; j < 10; j++) acc[j] = 0.f;

    for (int k0 = 0; k0 < 256; k0 += 64) {
        #pragma unroll
        for (int s = 0; s < 4; s++) {
            int l = tid + s * 256;
            int hr = l >> 4, hk = (l & 15) * 4;
            float4 hv = make_float4(0.f, 0.f, 0.f, 0.f);
            int gr = r0 + hr;
            if (gr < M) hv = *(const float4*)&h[(long long)gr * 256 + k0 + hk];
            hs[hr][hk] = hv.x; hs[hr][hk + 1] = hv.y; hs[hr][hk + 2] = hv.z; hs[hr][hk + 3] = hv.w;
        }
        #pragma unroll
        for (int s = 0; s < 10; s++) {
            int l = tid + s * 256;
            int wk = l / 40, wc = l % 40;
            Ws[wk][wc] = W[(k0 + wk) * 40 + wc];
        }
        __syncthreads();
        #pragma unroll
        for (int k = 0; k < 64; k++) {
            float a = hs[r][k];
            #pragma unroll
            for (int j = 0; j < 10; j++) acc[j] += a * Ws[k][cg * 10 + j];
        }
        __syncthreads();
    }
    int gr = r0 + r;
    if (gr < M) {
        #pragma unroll
        for (int j = 0; j < 10; j++)
            out[(long long)gr * 40 + cg * 10 + j] = acc[j] + bias[cg * 10 + j];
    }
}

// ---------------- launch ----------------
extern "C" void kernel_launch(void* const* d_in, const int* in_sizes, int n_in,
                              void* d_out, int out_size)
{
    const float* x     = (const float*)d_in[0];
    const float* W_in  = (const float*)d_in[2];
    const float* b_in  = (const float*)d_in[3];
    const float* ln0g  = (const float*)d_in[4];
    const float* ln0b  = (const float*)d_in[5];
    const float* Wv[2] = {(const float*)d_in[10], (const float*)d_in[18]};
    const float* bv[2] = {(const float*)d_in[11], (const float*)d_in[19]};
    const float* lng[2] = {(const float*)d_in[12], (const float*)d_in[20]};
    const float* lnb[2] = {(const float*)d_in[13], (const float*)d_in[21]};
    const float* W_out = (const float*)d_in[22];
    const float* b_out = (const float*)d_in[23];
    float* out = (float*)d_out;

    const int M = in_sizes[0] / 512;
    const int tiles = (M + 127) / 128;

    float *ph;
    __half *pA, *pH, *pBhi, *pBlo;
    cudaGetSymbolAddress((void**)&ph,   g_h);
    cudaGetSymbolAddress((void**)&pA,   g_A);
    cudaGetSymbolAddress((void**)&pH,   g_H);
    cudaGetSymbolAddress((void**)&pBhi, g_Bhi);
    cudaGetSymbolAddress((void**)&pBlo, g_Blo);

    cudaFuncSetAttribute(gemm_fused<0, 1>, cudaFuncAttributeMaxDynamicSharedMemorySize, DSMEM);
    cudaFuncSetAttribute(gemm_fused<1, 1>, cudaFuncAttributeMaxDynamicSharedMemorySize, DSMEM);
    cudaFuncSetAttribute(gemm_fused<1, 0>, cudaFuncAttributeMaxDynamicSharedMemorySize, DSMEM);

    // x -> fp16; W_in -> [256][512] transposed fp16 hi/lo
    conv_x<<<2048, 256>>>((const float4*)x, (long long)M * 512 / 4, pA);
    convW<<<512, 256>>>(W_in, pBhi, pBlo, 512);
    // h = relu(LN(x @ W_in + b_in)); emit h fp16
    gemm_fused<0, 1><<<tiles, 512, DSMEM>>>(pA, 512, pBhi, pBlo, b_in,
                                            ph, pH, ln0g, ln0b, M, 512);

    for (int l = 0; l < 2; l++) {
        convW<<<256, 256>>>(Wv[l], pBhi, pBlo, 256);
        // h = LN(0.5*(h@Wv+bv) + 0.5*h); l=0 re-emits fp16 h in place (race-free: own rows)
        if (l == 0)
            gemm_fused<1, 1><<<tiles, 512, DSMEM>>>(pH, 256, pBhi, pBlo, bv[l],
                                                    ph, pH, lng[l], lnb[l], M, 256);
        else
            gemm_fused<1, 0><<<tiles, 512, DSMEM>>>(pH, 256, pBhi, pBlo, bv[l],
                                                    ph, nullptr, lng[l], lnb[l], M, 256);
    }

    // out = h @ W_out + b_out
    out_gemm<<<(M + 63) / 64, 256>>>(ph, W_out, b_out, out, M);
}

// round 12
// speedup vs baseline: 2.0481x; 1.4065x over previous
#include <cuda_runtime.h>
#include <cuda_fp16.h>
#include <cstdint>

#define MAXN 100000

// ---------------- device scratch ----------------
__device__ float g_h[MAXN * 256];          // hidden state fp32
__device__ __half g_A[MAXN * 512];         // x fp16, lda=512
__device__ __half g_H[MAXN * 256];         // h fp16, lda=256
__device__ __half g_B[256 * 512];          // weight fp16, [n][k]
__device__ __half g_Wout[64 * 256];        // W_out fp16, [n][k], n padded to 64

// ---------------- PTX helpers (compute_103-safe) ----------------
__device__ __forceinline__ uint32_t smem_u32(const void* p) {
    uint32_t a;
    asm("{ .reg .u64 t; cvta.to.shared.u64 t, %1; cvt.u32.u64 %0, t; }" : "=r"(a) : "l"(p));
    return a;
}
__device__ __forceinline__ void cp16(uint32_t dst, const void* src) {
    asm volatile("cp.async.cg.shared.global [%0], [%1], 16;" :: "r"(dst), "l"(src));
}
__device__ __forceinline__ void cp_commit() {
    asm volatile("cp.async.commit_group;" ::: "memory");
}
__device__ __forceinline__ void cp_wait0() {
    asm volatile("cp.async.wait_group 0;" ::: "memory");
}
__device__ __forceinline__ void cp_wait1() {
    asm volatile("cp.async.wait_group 1;" ::: "memory");
}
__device__ __forceinline__ void cp_wait2() {
    asm volatile("cp.async.wait_group 2;" ::: "memory");
}
__device__ __forceinline__ void ldm_x4(uint32_t* r, uint32_t addr) {
    asm volatile("ldmatrix.sync.aligned.m8n8.x4.shared.b16 {%0,%1,%2,%3}, [%4];"
        : "=r"(r[0]), "=r"(r[1]), "=r"(r[2]), "=r"(r[3]) : "r"(addr));
}
__device__ __forceinline__ void mma16816(float* c, const uint32_t* a, const uint32_t* b) {
    asm volatile("mma.sync.aligned.m16n8k16.row.col.f32.f16.f16.f32 "
        "{%0,%1,%2,%3}, {%4,%5,%6,%7}, {%8,%9}, {%0,%1,%2,%3};"
        : "+f"(c[0]), "+f"(c[1]), "+f"(c[2]), "+f"(c[3])
        : "r"(a[0]), "r"(a[1]), "r"(a[2]), "r"(a[3]), "r"(b[0]), "r"(b[1]));
}

// Exact wait so buffer kt is ALWAYS complete: issued = min(kt+3, nk) groups,
// completed must be >= kt+1 -> allowed pending = min(kt+3, nk) - (kt+1).
__device__ __forceinline__ void cp_wait_for(int kt, int nk) {
    if (kt < nk - 2)       cp_wait2();
    else if (kt == nk - 2) cp_wait1();
    else                   cp_wait0();
}

// SMEM per stage (80B row stride): A @0 (10240), B @10240 (20480)
// Stage = 30720, FOUR stages = 122880.
#define STAGE 30720
#define DSMEM 122880

// ============ fused GEMM + LN: one CTA owns a full 128-row x 256-col output ============
// C = A[M,K] @ B[256,K]^T + bias (single fp16 product), then:
//   RESID=0: h = relu(LN(C));  RESID=1: h = LN(0.5*C + 0.5*h)
// EMIT=1: also write fp16 of h into Oh (same rows this CTA read -> race-free).
// grid = ceil(M/128), 512 threads (16 warps: 4m x 4n, 32x64 warp tile).
template<int RESID, int EMIT>
__global__ void __launch_bounds__(512, 1) gemm_fused(
    const __half* __restrict__ A, int lda,
    const __half* __restrict__ B,
    const float* __restrict__ bias,
    float* __restrict__ H,
    __half* __restrict__ Oh,
    const float* __restrict__ lng, const float* __restrict__ lnb,
    int M, int K)
{
    extern __shared__ char dsm[];
    __shared__ float2 red[128][4];
    const int tid = threadIdx.x;
    const int lane = tid & 31, wid = tid >> 5;
    const int wm = wid >> 2, wn = wid & 3;        // 4 x 4 warp grid
    const int row0 = blockIdx.x * 128;
    const int nk = K >> 5;                         // BK=32

    const uint32_t sbase = smem_u32(dsm);

    // cp.async: 3 x 16B chunks/thread/stage (A: 512 chunks, B: 1024 chunks)
    const __half* gP[3];
    uint32_t sO[3];
    #pragma unroll
    for (int i = 0; i < 3; i++) {
        int cid = tid + i * 512;
        if (cid < 512) {                 // A
            int r = cid >> 2, seg = cid & 3;
            int ar = min(row0 + r, M - 1);
            gP[i] = A + (long long)ar * lda + seg * 8;
            sO[i] = (uint32_t)(r * 80 + seg * 16);
        } else {                         // B
            int c2 = cid - 512;
            int r = c2 >> 2, seg = c2 & 3;
            gP[i] = B + (long long)r * K + seg * 8;
            sO[i] = 10240u + (uint32_t)(r * 80 + seg * 16);
        }
    }

    auto issue = [&](int kt) {
        uint32_t sb = sbase + (uint32_t)(kt & 3) * STAGE;
        long long adv = (long long)kt * 32;
        #pragma unroll
        for (int i = 0; i < 3; i++) cp16(sb + sO[i], gP[i] + adv);
        cp_commit();
    };

    float acc[2][8][4] = {};

    issue(0);
    issue(1);
    issue(2);

    const uint32_t aoff = (uint32_t)((lane & 15) * 80 + (lane >> 4) * 16);
    const uint32_t boff = (uint32_t)(((lane & 7) + ((lane >> 4) << 3)) * 80 + (((lane >> 3) & 1) << 4));
    const uint32_t awarp = (uint32_t)(wm * 32) * 80;
    const uint32_t bwarp = (uint32_t)(wn * 64) * 80;

    for (int kt = 0; kt < nk; kt++) {
        cp_wait_for(kt, nk);
        __syncthreads();

        uint32_t sb = sbase + (uint32_t)(kt & 3) * STAGE;
        #pragma unroll
        for (int kk = 0; kk < 2; kk++) {
            uint32_t sa = sb + awarp + kk * 32 + aoff;
            uint32_t ah[2][4];
            ldm_x4(ah[0], sa);
            ldm_x4(ah[1], sa + 1280);
            uint32_t sB0 = sb + 10240 + bwarp + kk * 32 + boff;
            #pragma unroll
            for (int g = 0; g < 4; g++) {
                uint32_t bh[4];
                ldm_x4(bh, sB0 + g * 1280);
                #pragma unroll
                for (int mt = 0; mt < 2; mt++) {
                    mma16816(acc[mt][2 * g],     ah[mt], &bh[0]);
                    mma16816(acc[mt][2 * g + 1], ah[mt], &bh[2]);
                }
            }
        }
        // issue into stage (kt+3)&3 == (kt-1)&3: its readers all passed the
        // barrier at the top of THIS iteration -> safe to overwrite.
        if (kt + 3 < nk) issue(kt + 3);
    }

    // -------- fragment-direct epilogue: bias + residual + LN (+relu) + stores --------
    // Thread owns rows: wm*32 + mt*16 + (lane>>2) + 8*hh ; cols: wn*64 + nt*8 + (lane&3)*2 {+0,1}
    const int cbase = wn * 64 + (lane & 3) * 2;
    #pragma unroll
    for (int mt = 0; mt < 2; mt++)
        #pragma unroll
        for (int hh = 0; hh < 2; hh++) {
            int row = wm * 32 + mt * 16 + (lane >> 2) + hh * 8;
            int gclamp = min(row0 + row, M - 1);
            float s = 0.f, s2 = 0.f;
            #pragma unroll
            for (int nt = 0; nt < 8; nt++) {
                int c = cbase + nt * 8;
                float2 bsv = *(const float2*)&bias[c];
                float x0 = acc[mt][nt][2 * hh], x1 = acc[mt][nt][2 * hh + 1];
                if (RESID) {
                    float2 hv = *(const float2*)&H[(long long)gclamp * 256 + c];
                    x0 = 0.5f * (x0 + bsv.x + hv.x);
                    x1 = 0.5f * (x1 + bsv.y + hv.y);
                } else {
                    x0 += bsv.x; x1 += bsv.y;
                }
                acc[mt][nt][2 * hh] = x0;
                acc[mt][nt][2 * hh + 1] = x1;
                s += x0 + x1;
                s2 += x0 * x0 + x1 * x1;
            }
            s  += __shfl_xor_sync(0xffffffffu, s, 1);
            s  += __shfl_xor_sync(0xffffffffu, s, 2);
            s2 += __shfl_xor_sync(0xffffffffu, s2, 1);
            s2 += __shfl_xor_sync(0xffffffffu, s2, 2);
            if ((lane & 3) == 0) red[row][wn] = make_float2(s, s2);
        }
    __syncthreads();

    #pragma unroll
    for (int mt = 0; mt < 2; mt++)
        #pragma unroll
        for (int hh = 0; hh < 2; hh++) {
            int row = wm * 32 + mt * 16 + (lane >> 2) + hh * 8;
            int grow = row0 + row;
            float2 r0 = red[row][0], r1 = red[row][1], r2 = red[row][2], r3 = red[row][3];
            float s  = r0.x + r1.x + r2.x + r3.x;
            float s2 = r0.y + r1.y + r2.y + r3.y;
            float mu = s * (1.f / 256.f);
            float var = s2 * (1.f / 256.f) - mu * mu;
            float rstd = rsqrtf(var + 1e-5f);
            if (grow < M) {
                #pragma unroll
                for (int nt = 0; nt < 8; nt++) {
                    int c = cbase + nt * 8;
                    float2 gv = *(const float2*)&lng[c];
                    float2 bv = *(const float2*)&lnb[c];
                    float y0 = gv.x * (acc[mt][nt][2 * hh] - mu) * rstd + bv.x;
                    float y1 = gv.y * (acc[mt][nt][2 * hh + 1] - mu) * rstd + bv.y;
                    if (!RESID) { y0 = fmaxf(y0, 0.f); y1 = fmaxf(y1, 0.f); }
                    *(float2*)&H[(long long)grow * 256 + c] = make_float2(y0, y1);
                    if (EMIT) {
                        __half h0 = __float2half(y0);
                        __half h1 = __float2half(y1);
                        uint32_t hp = (uint32_t)__half_as_ushort(h0) |
                                      ((uint32_t)__half_as_ushort(h1) << 16);
                        *(uint32_t*)&Oh[(long long)grow * 256 + c] = hp;
                    }
                }
            }
        }
}

// ============ out GEMM via mma: out[M,40] = Hfp16[M,256] @ Wout[64,256]^T + bias ====
// 256 threads, 8 warps (4m x 2n, 32x32 warp tile), K=256 (nk=8), 4-stage pipeline.
// SMEM per stage: A @0 (10240), B @10240 (5120). Stage 15360, x4 = 61440.
#define OSTAGE 15360
#define ODSMEM 61440
__global__ void __launch_bounds__(256, 1) out_mma(
    const __half* __restrict__ Hh, const __half* __restrict__ Wout,
    const float* __restrict__ bias, float* __restrict__ out, int M)
{
    extern __shared__ char dsm[];
    const int tid = threadIdx.x;
    const int lane = tid & 31, wid = tid >> 5;
    const int wm = wid >> 1, wn = wid & 1;        // 4 x 2 warp grid
    const int row0 = blockIdx.x * 128;
    const int nk = 8;

    const uint32_t sbase = smem_u32(dsm);

    // chunks/stage: A 512, B 256 -> 3 per thread
    const __half* gP[3];
    uint32_t sO[3];
    #pragma unroll
    for (int i = 0; i < 3; i++) {
        int cid = tid + i * 256;
        if (cid < 512) {                 // A
            int r = cid >> 2, seg = cid & 3;
            int ar = min(row0 + r, M - 1);
            gP[i] = Hh + (long long)ar * 256 + seg * 8;
            sO[i] = (uint32_t)(r * 80 + seg * 16);
        } else {                         // B (64 rows)
            int c2 = cid - 512;
            int r = c2 >> 2, seg = c2 & 3;
            gP[i] = Wout + (long long)r * 256 + seg * 8;
            sO[i] = 10240u + (uint32_t)(r * 80 + seg * 16);
        }
    }

    auto issue = [&](int kt) {
        uint32_t sb = sbase + (uint32_t)(kt & 3) * OSTAGE;
        long long adv = (long long)kt * 32;
        #pragma unroll
        for (int i = 0; i < 3; i++) cp16(sb + sO[i], gP[i] + adv);
        cp_commit();
    };

    float acc[2][4][4] = {};

    issue(0);
    issue(1);
    issue(2);

    const uint32_t aoff = (uint32_t)((lane & 15) * 80 + (lane >> 4) * 16);
    const uint32_t boff = (uint32_t)(((lane & 7) + ((lane >> 4) << 3)) * 80 + (((lane >> 3) & 1) << 4));
    const uint32_t awarp = (uint32_t)(wm * 32) * 80;
    const uint32_t bwarp = (uint32_t)(wn * 32) * 80;

    for (int kt = 0; kt < nk; kt++) {
        cp_wait_for(kt, nk);
        __syncthreads();

        uint32_t sb = sbase + (uint32_t)(kt & 3) * OSTAGE;
        #pragma unroll
        for (int kk = 0; kk < 2; kk++) {
            uint32_t sa = sb + awarp + kk * 32 + aoff;
            uint32_t ah[2][4];
            ldm_x4(ah[0], sa);
            ldm_x4(ah[1], sa + 1280);
            uint32_t sB0 = sb + 10240 + bwarp + kk * 32 + boff;
            #pragma unroll
            for (int g = 0; g < 2; g++) {
                uint32_t bh[4];
                ldm_x4(bh, sB0 + g * 1280);
                #pragma unroll
                for (int mt = 0; mt < 2; mt++) {
                    mma16816(acc[mt][2 * g],     ah[mt], &bh[0]);
                    mma16816(acc[mt][2 * g + 1], ah[mt], &bh[2]);
                }
            }
        }
        if (kt + 3 < nk) issue(kt + 3);
    }

    // epilogue: direct store (+bias), cols < 40 only
    const int cbase = wn * 32 + (lane & 3) * 2;
    #pragma unroll
    for (int mt = 0; mt < 2; mt++)
        #pragma unroll
        for (int hh = 0; hh < 2; hh++) {
            int grow = row0 + wm * 32 + mt * 16 + (lane >> 2) + hh * 8;
            if (grow >= M) continue;
            #pragma unroll
            for (int nt = 0; nt < 4; nt++) {
                int c = cbase + nt * 8;
                if (c + 1 < 40) {
                    float2 bv = *(const float2*)&bias[c];
                    float y0 = acc[mt][nt][2 * hh] + bv.x;
                    float y1 = acc[mt][nt][2 * hh + 1] + bv.y;
                    *(float2*)&out[(long long)grow * 40 + c] = make_float2(y0, y1);
                }
            }
        }
}

// ---------------- conversions ----------------
// x fp32 -> fp16
__global__ void conv_x(const float4* __restrict__ src, long long n4,
                       __half* __restrict__ dst)
{
    for (long long i = blockIdx.x * (long long)blockDim.x + threadIdx.x; i < n4;
         i += (long long)gridDim.x * blockDim.x) {
        float4 v = src[i];
        __half2 p0 = __floats2half2_rn(v.x, v.y);
        __half2 p1 = __floats2half2_rn(v.z, v.w);
        *(uint2*)&dst[i * 4] = make_uint2(*(uint32_t*)&p0, *(uint32_t*)&p1);
    }
}

// W [K,256] -> B [n][k] transposed fp16. grid = K blocks, 256 threads.
__global__ void convW(const float* __restrict__ W, __half* __restrict__ b, int K)
{
    int k = blockIdx.x, n = threadIdx.x;
    b[n * K + k] = __float2half(W[k * 256 + n]);
}

// W_out [256,40] -> [64][256] fp16 transposed, zero-padded n>=40. grid=256, 64 thr.
__global__ void convWout(const float* __restrict__ W, __half* __restrict__ b)
{
    int k = blockIdx.x, n = threadIdx.x;
    b[n * 256 + k] = (n < 40) ? __float2half(W[k * 40 + n]) : __ushort_as_half((unsigned short)0);
}

// ---------------- launch ----------------
extern "C" void kernel_launch(void* const* d_in, const int* in_sizes, int n_in,
                              void* d_out, int out_size)
{
    const float* x     = (const float*)d_in[0];
    const float* W_in  = (const float*)d_in[2];
    const float* b_in  = (const float*)d_in[3];
    const float* ln0g  = (const float*)d_in[4];
    const float* ln0b  = (const float*)d_in[5];
    const float* Wv[2] = {(const float*)d_in[10], (const float*)d_in[18]};
    const float* bv[2] = {(const float*)d_in[11], (const float*)d_in[19]};
    const float* lng[2] = {(const float*)d_in[12], (const float*)d_in[20]};
    const float* lnb[2] = {(const float*)d_in[13], (const float*)d_in[21]};
    const float* W_out = (const float*)d_in[22];
    const float* b_out = (const float*)d_in[23];
    float* out = (float*)d_out;

    const int M = in_sizes[0] / 512;
    const int tiles = (M + 127) / 128;

    float *ph;
    __half *pA, *pH, *pB, *pWo;
    cudaGetSymbolAddress((void**)&ph,  g_h);
    cudaGetSymbolAddress((void**)&pA,  g_A);
    cudaGetSymbolAddress((void**)&pH,  g_H);
    cudaGetSymbolAddress((void**)&pB,  g_B);
    cudaGetSymbolAddress((void**)&pWo, g_Wout);

    cudaFuncSetAttribute(gemm_fused<0, 1>, cudaFuncAttributeMaxDynamicSharedMemorySize, DSMEM);
    cudaFuncSetAttribute(gemm_fused<1, 1>, cudaFuncAttributeMaxDynamicSharedMemorySize, DSMEM);
    cudaFuncSetAttribute(out_mma, cudaFuncAttributeMaxDynamicSharedMemorySize, ODSMEM);

    // x -> fp16; W_in -> [256][512] transposed fp16; W_out -> [64][256] fp16
    conv_x<<<2048, 256>>>((const float4*)x, (long long)M * 512 / 4, pA);
    convW<<<512, 256>>>(W_in, pB, 512);
    convWout<<<256, 64>>>(W_out, pWo);
    // h = relu(LN(x @ W_in + b_in)); emit h fp16
    gemm_fused<0, 1><<<tiles, 512, DSMEM>>>(pA, 512, pB, b_in,
                                            ph, pH, ln0g, ln0b, M, 512);

    for (int l = 0; l < 2; l++) {
        convW<<<256, 256>>>(Wv[l], pB, 256);
        // h = LN(0.5*(h@Wv+bv) + 0.5*h); both layers emit fp16 h (layer 1 feeds out_mma)
        gemm_fused<1, 1><<<tiles, 512, DSMEM>>>(pH, 256, pB, bv[l],
                                                ph, pH, lng[l], lnb[l], M, 256);
    }

    // out = h @ W_out + b_out  (fp16 tensor-core)
    out_mma<<<tiles, 256, ODSMEM>>>(pH, pWo, b_out, out, M);
}

// round 13
// speedup vs baseline: 2.1182x; 1.0342x over previous
#include <cuda_runtime.h>
#include <cuda_fp16.h>
#include <cstdint>

#define MAXN 100000

// ---------------- device scratch ----------------
__device__ float g_h[MAXN * 256];          // hidden state fp32
__device__ __half g_A[MAXN * 512];         // x fp16, lda=512
__device__ __half g_H[MAXN * 256];         // h fp16, lda=256
__device__ __half g_B[256 * 512];          // weight fp16, [n][k]
__device__ __half g_Wout[64 * 256];        // W_out fp16, [n][k], n padded to 64

// ---------------- PTX helpers (compute_103-safe) ----------------
__device__ __forceinline__ uint32_t smem_u32(const void* p) {
    uint32_t a;
    asm("{ .reg .u64 t; cvta.to.shared.u64 t, %1; cvt.u32.u64 %0, t; }" : "=r"(a) : "l"(p));
    return a;
}
__device__ __forceinline__ void cp16(uint32_t dst, const void* src) {
    asm volatile("cp.async.cg.shared.global [%0], [%1], 16;" :: "r"(dst), "l"(src));
}
__device__ __forceinline__ void cp_commit() {
    asm volatile("cp.async.commit_group;" ::: "memory");
}
__device__ __forceinline__ void cp_wait0() {
    asm volatile("cp.async.wait_group 0;" ::: "memory");
}
__device__ __forceinline__ void cp_wait1() {
    asm volatile("cp.async.wait_group 1;" ::: "memory");
}
__device__ __forceinline__ void cp_wait2() {
    asm volatile("cp.async.wait_group 2;" ::: "memory");
}
__device__ __forceinline__ void ldm_x4(uint32_t* r, uint32_t addr) {
    asm volatile("ldmatrix.sync.aligned.m8n8.x4.shared.b16 {%0,%1,%2,%3}, [%4];"
        : "=r"(r[0]), "=r"(r[1]), "=r"(r[2]), "=r"(r[3]) : "r"(addr));
}
__device__ __forceinline__ void mma16816(float* c, const uint32_t* a, const uint32_t* b) {
    asm volatile("mma.sync.aligned.m16n8k16.row.col.f32.f16.f16.f32 "
        "{%0,%1,%2,%3}, {%4,%5,%6,%7}, {%8,%9}, {%0,%1,%2,%3};"
        : "+f"(c[0]), "+f"(c[1]), "+f"(c[2]), "+f"(c[3])
        : "r"(a[0]), "r"(a[1]), "r"(a[2]), "r"(a[3]), "r"(b[0]), "r"(b[1]));
}

// Exact wait so buffer kt is ALWAYS complete: issued = min(kt+3, nk) groups,
// completed must be >= kt+1 -> allowed pending = min(kt+3, nk) - (kt+1).
__device__ __forceinline__ void cp_wait_for(int kt, int nk) {
    if (kt < nk - 2)       cp_wait2();
    else if (kt == nk - 2) cp_wait1();
    else                   cp_wait0();
}

// SMEM per stage (80B row stride): A(64 rows) @0 (5120), B(256 rows) @5120 (20480)
// Stage = 25600, FOUR stages = 102400 -> TWO CTAs per SM.
#define STAGE 25600
#define DSMEM 102400

// ============ fused GEMM + LN: one CTA owns a full 64-row x 256-col output ============
// C = A[M,K] @ B[256,K]^T + bias (single fp16 product), then:
//   RESID=0: h = relu(LN(C));  RESID=1: h = LN(0.5*C + 0.5*h)
// EMIT=1: also write fp16 of h into Oh (same rows this CTA read -> race-free).
// grid = ceil(M/64), 256 threads (8 warps: 2m x 4n, 32x64 warp tile).
template<int RESID, int EMIT>
__global__ void __launch_bounds__(256, 2) gemm_fused(
    const __half* __restrict__ A, int lda,
    const __half* __restrict__ B,
    const float* __restrict__ bias,
    float* __restrict__ H,
    __half* __restrict__ Oh,
    const float* __restrict__ lng, const float* __restrict__ lnb,
    int M, int K)
{
    extern __shared__ char dsm[];
    __shared__ float2 red[64][4];
    const int tid = threadIdx.x;
    const int lane = tid & 31, wid = tid >> 5;
    const int wm = wid >> 2, wn = wid & 3;        // 2 x 4 warp grid
    const int row0 = blockIdx.x * 64;
    const int nk = K >> 5;                         // BK=32

    const uint32_t sbase = smem_u32(dsm);

    // cp.async: 5 x 16B chunks/thread/stage (A: 256 chunks, B: 1024 chunks)
    const __half* gP[5];
    uint32_t sO[5];
    #pragma unroll
    for (int i = 0; i < 5; i++) {
        int cid = tid + i * 256;
        if (cid < 256) {                 // A (64 rows)
            int r = cid >> 2, seg = cid & 3;
            int ar = min(row0 + r, M - 1);
            gP[i] = A + (long long)ar * lda + seg * 8;
            sO[i] = (uint32_t)(r * 80 + seg * 16);
        } else {                         // B (256 rows)
            int c2 = cid - 256;
            int r = c2 >> 2, seg = c2 & 3;
            gP[i] = B + (long long)r * K + seg * 8;
            sO[i] = 5120u + (uint32_t)(r * 80 + seg * 16);
        }
    }

    auto issue = [&](int kt) {
        uint32_t sb = sbase + (uint32_t)(kt & 3) * STAGE;
        long long adv = (long long)kt * 32;
        #pragma unroll
        for (int i = 0; i < 5; i++) cp16(sb + sO[i], gP[i] + adv);
        cp_commit();
    };

    float acc[2][8][4] = {};

    issue(0);
    issue(1);
    issue(2);

    const uint32_t aoff = (uint32_t)((lane & 15) * 80 + (lane >> 4) * 16);
    const uint32_t boff = (uint32_t)(((lane & 7) + ((lane >> 4) << 3)) * 80 + (((lane >> 3) & 1) << 4));
    const uint32_t awarp = (uint32_t)(wm * 32) * 80;
    const uint32_t bwarp = (uint32_t)(wn * 64) * 80;

    for (int kt = 0; kt < nk; kt++) {
        cp_wait_for(kt, nk);
        __syncthreads();

        uint32_t sb = sbase + (uint32_t)(kt & 3) * STAGE;
        #pragma unroll
        for (int kk = 0; kk < 2; kk++) {
            uint32_t sa = sb + awarp + kk * 32 + aoff;
            uint32_t ah[2][4];
            ldm_x4(ah[0], sa);
            ldm_x4(ah[1], sa + 1280);
            uint32_t sB0 = sb + 5120 + bwarp + kk * 32 + boff;
            #pragma unroll
            for (int g = 0; g < 4; g++) {
                uint32_t bh[4];
                ldm_x4(bh, sB0 + g * 1280);
                #pragma unroll
                for (int mt = 0; mt < 2; mt++) {
                    mma16816(acc[mt][2 * g],     ah[mt], &bh[0]);
                    mma16816(acc[mt][2 * g + 1], ah[mt], &bh[2]);
                }
            }
        }
        // issue into stage (kt+3)&3 == (kt-1)&3: its readers all passed the
        // barrier at the top of THIS iteration -> safe to overwrite.
        if (kt + 3 < nk) issue(kt + 3);
    }

    // -------- fragment-direct epilogue: bias + residual + LN (+relu) + stores --------
    // Thread owns rows: wm*32 + mt*16 + (lane>>2) + 8*hh ; cols: wn*64 + nt*8 + (lane&3)*2 {+0,1}
    const int cbase = wn * 64 + (lane & 3) * 2;
    #pragma unroll
    for (int mt = 0; mt < 2; mt++)
        #pragma unroll
        for (int hh = 0; hh < 2; hh++) {
            int row = wm * 32 + mt * 16 + (lane >> 2) + hh * 8;
            int gclamp = min(row0 + row, M - 1);
            float s = 0.f, s2 = 0.f;
            #pragma unroll
            for (int nt = 0; nt < 8; nt++) {
                int c = cbase + nt * 8;
                float2 bsv = *(const float2*)&bias[c];
                float x0 = acc[mt][nt][2 * hh], x1 = acc[mt][nt][2 * hh + 1];
                if (RESID) {
                    float2 hv = *(const float2*)&H[(long long)gclamp * 256 + c];
                    x0 = 0.5f * (x0 + bsv.x + hv.x);
                    x1 = 0.5f * (x1 + bsv.y + hv.y);
                } else {
                    x0 += bsv.x; x1 += bsv.y;
                }
                acc[mt][nt][2 * hh] = x0;
                acc[mt][nt][2 * hh + 1] = x1;
                s += x0 + x1;
                s2 += x0 * x0 + x1 * x1;
            }
            s  += __shfl_xor_sync(0xffffffffu, s, 1);
            s  += __shfl_xor_sync(0xffffffffu, s, 2);
            s2 += __shfl_xor_sync(0xffffffffu, s2, 1);
            s2 += __shfl_xor_sync(0xffffffffu, s2, 2);
            if ((lane & 3) == 0) red[row][wn] = make_float2(s, s2);
        }
    __syncthreads();

    #pragma unroll
    for (int mt = 0; mt < 2; mt++)
        #pragma unroll
        for (int hh = 0; hh < 2; hh++) {
            int row = wm * 32 + mt * 16 + (lane >> 2) + hh * 8;
            int grow = row0 + row;
            float2 r0 = red[row][0], r1 = red[row][1], r2 = red[row][2], r3 = red[row][3];
            float s  = r0.x + r1.x + r2.x + r3.x;
            float s2 = r0.y + r1.y + r2.y + r3.y;
            float mu = s * (1.f / 256.f);
            float var = s2 * (1.f / 256.f) - mu * mu;
            float rstd = rsqrtf(var + 1e-5f);
            if (grow < M) {
                #pragma unroll
                for (int nt = 0; nt < 8; nt++) {
                    int c = cbase + nt * 8;
                    float2 gv = *(const float2*)&lng[c];
                    float2 bv = *(const float2*)&lnb[c];
                    float y0 = gv.x * (acc[mt][nt][2 * hh] - mu) * rstd + bv.x;
                    float y1 = gv.y * (acc[mt][nt][2 * hh + 1] - mu) * rstd + bv.y;
                    if (!RESID) { y0 = fmaxf(y0, 0.f); y1 = fmaxf(y1, 0.f); }
                    *(float2*)&H[(long long)grow * 256 + c] = make_float2(y0, y1);
                    if (EMIT) {
                        __half h0 = __float2half(y0);
                        __half h1 = __float2half(y1);
                        uint32_t hp = (uint32_t)__half_as_ushort(h0) |
                                      ((uint32_t)__half_as_ushort(h1) << 16);
                        *(uint32_t*)&Oh[(long long)grow * 256 + c] = hp;
                    }
                }
            }
        }
}

// ============ out GEMM via mma: out[M,40] = Hfp16[M,256] @ Wout[64,256]^T + bias ====
// 256 threads, 8 warps (4m x 2n, 32x32 warp tile), K=256 (nk=8), 4-stage pipeline.
// SMEM per stage: A @0 (10240), B @10240 (5120). Stage 15360, x4 = 61440.
#define OSTAGE 15360
#define ODSMEM 61440
__global__ void __launch_bounds__(256, 1) out_mma(
    const __half* __restrict__ Hh, const __half* __restrict__ Wout,
    const float* __restrict__ bias, float* __restrict__ out, int M)
{
    extern __shared__ char dsm[];
    const int tid = threadIdx.x;
    const int lane = tid & 31, wid = tid >> 5;
    const int wm = wid >> 1, wn = wid & 1;        // 4 x 2 warp grid
    const int row0 = blockIdx.x * 128;
    const int nk = 8;

    const uint32_t sbase = smem_u32(dsm);

    // chunks/stage: A 512, B 256 -> 3 per thread
    const __half* gP[3];
    uint32_t sO[3];
    #pragma unroll
    for (int i = 0; i < 3; i++) {
        int cid = tid + i * 256;
        if (cid < 512) {                 // A
            int r = cid >> 2, seg = cid & 3;
            int ar = min(row0 + r, M - 1);
            gP[i] = Hh + (long long)ar * 256 + seg * 8;
            sO[i] = (uint32_t)(r * 80 + seg * 16);
        } else {                         // B (64 rows)
            int c2 = cid - 512;
            int r = c2 >> 2, seg = c2 & 3;
            gP[i] = Wout + (long long)r * 256 + seg * 8;
            sO[i] = 10240u + (uint32_t)(r * 80 + seg * 16);
        }
    }

    auto issue = [&](int kt) {
        uint32_t sb = sbase + (uint32_t)(kt & 3) * OSTAGE;
        long long adv = (long long)kt * 32;
        #pragma unroll
        for (int i = 0; i < 3; i++) cp16(sb + sO[i], gP[i] + adv);
        cp_commit();
    };

    float acc[2][4][4] = {};

    issue(0);
    issue(1);
    issue(2);

    const uint32_t aoff = (uint32_t)((lane & 15) * 80 + (lane >> 4) * 16);
    const uint32_t boff = (uint32_t)(((lane & 7) + ((lane >> 4) << 3)) * 80 + (((lane >> 3) & 1) << 4));
    const uint32_t awarp = (uint32_t)(wm * 32) * 80;
    const uint32_t bwarp = (uint32_t)(wn * 32) * 80;

    for (int kt = 0; kt < nk; kt++) {
        cp_wait_for(kt, nk);
        __syncthreads();

        uint32_t sb = sbase + (uint32_t)(kt & 3) * OSTAGE;
        #pragma unroll
        for (int kk = 0; kk < 2; kk++) {
            uint32_t sa = sb + awarp + kk * 32 + aoff;
            uint32_t ah[2][4];
            ldm_x4(ah[0], sa);
            ldm_x4(ah[1], sa + 1280);
            uint32_t sB0 = sb + 10240 + bwarp + kk * 32 + boff;
            #pragma unroll
            for (int g = 0; g < 2; g++) {
                uint32_t bh[4];
                ldm_x4(bh, sB0 + g * 1280);
                #pragma unroll
                for (int mt = 0; mt < 2; mt++) {
                    mma16816(acc[mt][2 * g],     ah[mt], &bh[0]);
                    mma16816(acc[mt][2 * g + 1], ah[mt], &bh[2]);
                }
            }
        }
        if (kt + 3 < nk) issue(kt + 3);
    }

    // epilogue: direct store (+bias), cols < 40 only
    const int cbase = wn * 32 + (lane & 3) * 2;
    #pragma unroll
    for (int mt = 0; mt < 2; mt++)
        #pragma unroll
        for (int hh = 0; hh < 2; hh++) {
            int grow = row0 + wm * 32 + mt * 16 + (lane >> 2) + hh * 8;
            if (grow >= M) continue;
            #pragma unroll
            for (int nt = 0; nt < 4; nt++) {
                int c = cbase + nt * 8;
                if (c + 1 < 40) {
                    float2 bv = *(const float2*)&bias[c];
                    float y0 = acc[mt][nt][2 * hh] + bv.x;
                    float y1 = acc[mt][nt][2 * hh + 1] + bv.y;
                    *(float2*)&out[(long long)grow * 40 + c] = make_float2(y0, y1);
                }
            }
        }
}

// ---------------- conversions ----------------
// x fp32 -> fp16
__global__ void conv_x(const float4* __restrict__ src, long long n4,
                       __half* __restrict__ dst)
{
    for (long long i = blockIdx.x * (long long)blockDim.x + threadIdx.x; i < n4;
         i += (long long)gridDim.x * blockDim.x) {
        float4 v = src[i];
        __half2 p0 = __floats2half2_rn(v.x, v.y);
        __half2 p1 = __floats2half2_rn(v.z, v.w);
        *(uint2*)&dst[i * 4] = make_uint2(*(uint32_t*)&p0, *(uint32_t*)&p1);
    }
}

// W [K,256] -> B [n][k] transposed fp16. grid = K blocks, 256 threads.
__global__ void convW(const float* __restrict__ W, __half* __restrict__ b, int K)
{
    int k = blockIdx.x, n = threadIdx.x;
    b[n * K + k] = __float2half(W[k * 256 + n]);
}

// W_out [256,40] -> [64][256] fp16 transposed, zero-padded n>=40. grid=256, 64 thr.
__global__ void convWout(const float* __restrict__ W, __half* __restrict__ b)
{
    int k = blockIdx.x, n = threadIdx.x;
    b[n * 256 + k] = (n < 40) ? __float2half(W[k * 40 + n]) : __ushort_as_half((unsigned short)0);
}

// ---------------- launch ----------------
extern "C" void kernel_launch(void* const* d_in, const int* in_sizes, int n_in,
                              void* d_out, int out_size)
{
    const float* x     = (const float*)d_in[0];
    const float* W_in  = (const float*)d_in[2];
    const float* b_in  = (const float*)d_in[3];
    const float* ln0g  = (const float*)d_in[4];
    const float* ln0b  = (const float*)d_in[5];
    const float* Wv[2] = {(const float*)d_in[10], (const float*)d_in[18]};
    const float* bv[2] = {(const float*)d_in[11], (const float*)d_in[19]};
    const float* lng[2] = {(const float*)d_in[12], (const float*)d_in[20]};
    const float* lnb[2] = {(const float*)d_in[13], (const float*)d_in[21]};
    const float* W_out = (const float*)d_in[22];
    const float* b_out = (const float*)d_in[23];
    float* out = (float*)d_out;

    const int M = in_sizes[0] / 512;
    const int tiles64 = (M + 63) / 64;
    const int tiles128 = (M + 127) / 128;

    float *ph;
    __half *pA, *pH, *pB, *pWo;
    cudaGetSymbolAddress((void**)&ph,  g_h);
    cudaGetSymbolAddress((void**)&pA,  g_A);
    cudaGetSymbolAddress((void**)&pH,  g_H);
    cudaGetSymbolAddress((void**)&pB,  g_B);
    cudaGetSymbolAddress((void**)&pWo, g_Wout);

    cudaFuncSetAttribute(gemm_fused<0, 1>, cudaFuncAttributeMaxDynamicSharedMemorySize, DSMEM);
    cudaFuncSetAttribute(gemm_fused<1, 1>, cudaFuncAttributeMaxDynamicSharedMemorySize, DSMEM);
    cudaFuncSetAttribute(out_mma, cudaFuncAttributeMaxDynamicSharedMemorySize, ODSMEM);

    // x -> fp16; W_in -> [256][512] transposed fp16; W_out -> [64][256] fp16
    conv_x<<<2048, 256>>>((const float4*)x, (long long)M * 512 / 4, pA);
    convW<<<512, 256>>>(W_in, pB, 512);
    convWout<<<256, 64>>>(W_out, pWo);
    // h = relu(LN(x @ W_in + b_in)); emit h fp16
    gemm_fused<0, 1><<<tiles64, 256, DSMEM>>>(pA, 512, pB, b_in,
                                              ph, pH, ln0g, ln0b, M, 512);

    for (int l = 0; l < 2; l++) {
        convW<<<256, 256>>>(Wv[l], pB, 256);
        // h = LN(0.5*(h@Wv+bv) + 0.5*h); both layers emit fp16 h (layer 1 feeds out_mma)
        gemm_fused<1, 1><<<tiles64, 256, DSMEM>>>(pH, 256, pB, bv[l],
                                                  ph, pH, lng[l], lnb[l], M, 256);
    }

    // out = h @ W_out + b_out  (fp16 tensor-core)
    out_mma<<<tiles128, 256, ODSMEM>>>(pH, pWo, b_out, out, M);
}

// round 14
// speedup vs baseline: 2.5077x; 1.1839x over previous
#include <cuda_runtime.h>
#include <cuda_fp16.h>
#include <cstdint>

#define MAXN 100000

// ---------------- device scratch ----------------
__device__ __half g_A[MAXN * 512];         // x fp16, lda=512
__device__ __half g_H[MAXN * 256];         // h fp16 (ONLY representation of h)
__device__ __half g_B[256 * 512];          // weight fp16, [n][k]
__device__ __half g_Wout[64 * 256];        // W_out fp16, [n][k], n padded to 64

// ---------------- PTX helpers (compute_103-safe) ----------------
__device__ __forceinline__ uint32_t smem_u32(const void* p) {
    uint32_t a;
    asm("{ .reg .u64 t; cvta.to.shared.u64 t, %1; cvt.u32.u64 %0, t; }" : "=r"(a) : "l"(p));
    return a;
}
__device__ __forceinline__ void cp16(uint32_t dst, const void* src) {
    asm volatile("cp.async.cg.shared.global [%0], [%1], 16;" :: "r"(dst), "l"(src));
}
__device__ __forceinline__ void cp_commit() {
    asm volatile("cp.async.commit_group;" ::: "memory");
}
__device__ __forceinline__ void cp_wait0() {
    asm volatile("cp.async.wait_group 0;" ::: "memory");
}
__device__ __forceinline__ void cp_wait1() {
    asm volatile("cp.async.wait_group 1;" ::: "memory");
}
__device__ __forceinline__ void cp_wait2() {
    asm volatile("cp.async.wait_group 2;" ::: "memory");
}
__device__ __forceinline__ void ldm_x4(uint32_t* r, uint32_t addr) {
    asm volatile("ldmatrix.sync.aligned.m8n8.x4.shared.b16 {%0,%1,%2,%3}, [%4];"
        : "=r"(r[0]), "=r"(r[1]), "=r"(r[2]), "=r"(r[3]) : "r"(addr));
}
__device__ __forceinline__ void mma16816(float* c, const uint32_t* a, const uint32_t* b) {
    asm volatile("mma.sync.aligned.m16n8k16.row.col.f32.f16.f16.f32 "
        "{%0,%1,%2,%3}, {%4,%5,%6,%7}, {%8,%9}, {%0,%1,%2,%3};"
        : "+f"(c[0]), "+f"(c[1]), "+f"(c[2]), "+f"(c[3])
        : "r"(a[0]), "r"(a[1]), "r"(a[2]), "r"(a[3]), "r"(b[0]), "r"(b[1]));
}

// Exact wait so buffer kt is ALWAYS complete: issued = min(kt+3, nk) groups,
// completed must be >= kt+1 -> allowed pending = min(kt+3, nk) - (kt+1).
__device__ __forceinline__ void cp_wait_for(int kt, int nk) {
    if (kt < nk - 2)       cp_wait2();
    else if (kt == nk - 2) cp_wait1();
    else                   cp_wait0();
}

// SMEM per stage (80B row stride): A(64 rows) @0 (5120), B(256 rows) @5120 (20480)
// Stage = 25600, FOUR stages = 102400 -> TWO CTAs per SM.
#define STAGE 25600
#define DSMEM 102400

// ============ fused GEMM + LN: one CTA owns a full 64-row x 256-col output ============
// C = A[M,K] @ B[256,K]^T + bias (single fp16 product), then:
//   RESID=0: h = relu(LN(C));  RESID=1: h = LN(0.5*C + 0.5*h)   [h fp16 in Oh]
// h written back fp16 to Oh (same rows this CTA read as A / residual -> race-free).
// grid = ceil(M/64), 256 threads (8 warps: 2m x 4n, 32x64 warp tile).
template<int RESID>
__global__ void __launch_bounds__(256, 2) gemm_fused(
    const __half* __restrict__ A, int lda,
    const __half* __restrict__ B,
    const float* __restrict__ bias,
    __half* __restrict__ Oh,
    const float* __restrict__ lng, const float* __restrict__ lnb,
    int M, int K)
{
    extern __shared__ char dsm[];
    __shared__ float2 red[64][4];
    const int tid = threadIdx.x;
    const int lane = tid & 31, wid = tid >> 5;
    const int wm = wid >> 2, wn = wid & 3;        // 2 x 4 warp grid
    const int row0 = blockIdx.x * 64;
    const int nk = K >> 5;                         // BK=32

    const uint32_t sbase = smem_u32(dsm);

    // cp.async: 5 x 16B chunks/thread/stage (A: 256 chunks, B: 1024 chunks)
    const __half* gP[5];
    uint32_t sO[5];
    #pragma unroll
    for (int i = 0; i < 5; i++) {
        int cid = tid + i * 256;
        if (cid < 256) {                 // A (64 rows)
            int r = cid >> 2, seg = cid & 3;
            int ar = min(row0 + r, M - 1);
            gP[i] = A + (long long)ar * lda + seg * 8;
            sO[i] = (uint32_t)(r * 80 + seg * 16);
        } else {                         // B (256 rows)
            int c2 = cid - 256;
            int r = c2 >> 2, seg = c2 & 3;
            gP[i] = B + (long long)r * K + seg * 8;
            sO[i] = 5120u + (uint32_t)(r * 80 + seg * 16);
        }
    }

    auto issue = [&](int kt) {
        uint32_t sb = sbase + (uint32_t)(kt & 3) * STAGE;
        long long adv = (long long)kt * 32;
        #pragma unroll
        for (int i = 0; i < 5; i++) cp16(sb + sO[i], gP[i] + adv);
        cp_commit();
    };

    float acc[2][8][4] = {};

    issue(0);
    issue(1);
    issue(2);

    const uint32_t aoff = (uint32_t)((lane & 15) * 80 + (lane >> 4) * 16);
    const uint32_t boff = (uint32_t)(((lane & 7) + ((lane >> 4) << 3)) * 80 + (((lane >> 3) & 1) << 4));
    const uint32_t awarp = (uint32_t)(wm * 32) * 80;
    const uint32_t bwarp = (uint32_t)(wn * 64) * 80;

    for (int kt = 0; kt < nk; kt++) {
        cp_wait_for(kt, nk);
        __syncthreads();

        uint32_t sb = sbase + (uint32_t)(kt & 3) * STAGE;
        #pragma unroll
        for (int kk = 0; kk < 2; kk++) {
            uint32_t sa = sb + awarp + kk * 32 + aoff;
            uint32_t ah[2][4];
            ldm_x4(ah[0], sa);
            ldm_x4(ah[1], sa + 1280);
            uint32_t sB0 = sb + 5120 + bwarp + kk * 32 + boff;
            #pragma unroll
            for (int g = 0; g < 4; g++) {
                uint32_t bh[4];
                ldm_x4(bh, sB0 + g * 1280);
                #pragma unroll
                for (int mt = 0; mt < 2; mt++) {
                    mma16816(acc[mt][2 * g],     ah[mt], &bh[0]);
                    mma16816(acc[mt][2 * g + 1], ah[mt], &bh[2]);
                }
            }
        }
        // issue into stage (kt+3)&3 == (kt-1)&3: its readers all passed the
        // barrier at the top of THIS iteration -> safe to overwrite.
        if (kt + 3 < nk) issue(kt + 3);
    }

    // -------- fragment-direct epilogue: bias + residual + LN (+relu) + fp16 store ----
    // Thread owns rows: wm*32 + mt*16 + (lane>>2) + 8*hh ; cols: wn*64 + nt*8 + (lane&3)*2 {+0,1}
    const int cbase = wn * 64 + (lane & 3) * 2;
    #pragma unroll
    for (int mt = 0; mt < 2; mt++)
        #pragma unroll
        for (int hh = 0; hh < 2; hh++) {
            int row = wm * 32 + mt * 16 + (lane >> 2) + hh * 8;
            int gclamp = min(row0 + row, M - 1);
            float s = 0.f, s2 = 0.f;
            #pragma unroll
            for (int nt = 0; nt < 8; nt++) {
                int c = cbase + nt * 8;
                float2 bsv = *(const float2*)&bias[c];
                float x0 = acc[mt][nt][2 * hh], x1 = acc[mt][nt][2 * hh + 1];
                if (RESID) {
                    uint32_t hp = *(const uint32_t*)&Oh[(long long)gclamp * 256 + c];
                    __half2 hv = *(__half2*)&hp;
                    x0 = 0.5f * (x0 + bsv.x + __half2float(hv.x));
                    x1 = 0.5f * (x1 + bsv.y + __half2float(hv.y));
                } else {
                    x0 += bsv.x; x1 += bsv.y;
                }
                acc[mt][nt][2 * hh] = x0;
                acc[mt][nt][2 * hh + 1] = x1;
                s += x0 + x1;
                s2 += x0 * x0 + x1 * x1;
            }
            s  += __shfl_xor_sync(0xffffffffu, s, 1);
            s  += __shfl_xor_sync(0xffffffffu, s, 2);
            s2 += __shfl_xor_sync(0xffffffffu, s2, 1);
            s2 += __shfl_xor_sync(0xffffffffu, s2, 2);
            if ((lane & 3) == 0) red[row][wn] = make_float2(s, s2);
        }
    __syncthreads();

    #pragma unroll
    for (int mt = 0; mt < 2; mt++)
        #pragma unroll
        for (int hh = 0; hh < 2; hh++) {
            int row = wm * 32 + mt * 16 + (lane >> 2) + hh * 8;
            int grow = row0 + row;
            float2 r0 = red[row][0], r1 = red[row][1], r2 = red[row][2], r3 = red[row][3];
            float s  = r0.x + r1.x + r2.x + r3.x;
            float s2 = r0.y + r1.y + r2.y + r3.y;
            float mu = s * (1.f / 256.f);
            float var = s2 * (1.f / 256.f) - mu * mu;
            float rstd = rsqrtf(var + 1e-5f);
            if (grow < M) {
                #pragma unroll
                for (int nt = 0; nt < 8; nt++) {
                    int c = cbase + nt * 8;
                    float2 gv = *(const float2*)&lng[c];
                    float2 bv = *(const float2*)&lnb[c];
                    float y0 = gv.x * (acc[mt][nt][2 * hh] - mu) * rstd + bv.x;
                    float y1 = gv.y * (acc[mt][nt][2 * hh + 1] - mu) * rstd + bv.y;
                    if (!RESID) { y0 = fmaxf(y0, 0.f); y1 = fmaxf(y1, 0.f); }
                    __half h0 = __float2half(y0);
                    __half h1 = __float2half(y1);
                    uint32_t hp = (uint32_t)__half_as_ushort(h0) |
                                  ((uint32_t)__half_as_ushort(h1) << 16);
                    *(uint32_t*)&Oh[(long long)grow * 256 + c] = hp;
                }
            }
        }
}

// ============ out GEMM via mma: out[M,40] = Hfp16[M,256] @ Wout[64,256]^T + bias ====
// 256 threads, 8 warps (4m x 2n, 32x32 warp tile), K=256 (nk=8), 4-stage pipeline.
// SMEM per stage: A @0 (10240), B @10240 (5120). Stage 15360, x4 = 61440.
#define OSTAGE 15360
#define ODSMEM 61440
__global__ void __launch_bounds__(256, 1) out_mma(
    const __half* __restrict__ Hh, const __half* __restrict__ Wout,
    const float* __restrict__ bias, float* __restrict__ out, int M)
{
    extern __shared__ char dsm[];
    const int tid = threadIdx.x;
    const int lane = tid & 31, wid = tid >> 5;
    const int wm = wid >> 1, wn = wid & 1;        // 4 x 2 warp grid
    const int row0 = blockIdx.x * 128;
    const int nk = 8;

    const uint32_t sbase = smem_u32(dsm);

    // chunks/stage: A 512, B 256 -> 3 per thread
    const __half* gP[3];
    uint32_t sO[3];
    #pragma unroll
    for (int i = 0; i < 3; i++) {
        int cid = tid + i * 256;
        if (cid < 512) {                 // A
            int r = cid >> 2, seg = cid & 3;
            int ar = min(row0 + r, M - 1);
            gP[i] = Hh + (long long)ar * 256 + seg * 8;
            sO[i] = (uint32_t)(r * 80 + seg * 16);
        } else {                         // B (64 rows)
            int c2 = cid - 512;
            int r = c2 >> 2, seg = c2 & 3;
            gP[i] = Wout + (long long)r * 256 + seg * 8;
            sO[i] = 10240u + (uint32_t)(r * 80 + seg * 16);
        }
    }

    auto issue = [&](int kt) {
        uint32_t sb = sbase + (uint32_t)(kt & 3) * OSTAGE;
        long long adv = (long long)kt * 32;
        #pragma unroll
        for (int i = 0; i < 3; i++) cp16(sb + sO[i], gP[i] + adv);
        cp_commit();
    };

    float acc[2][4][4] = {};

    issue(0);
    issue(1);
    issue(2);

    const uint32_t aoff = (uint32_t)((lane & 15) * 80 + (lane >> 4) * 16);
    const uint32_t boff = (uint32_t)(((lane & 7) + ((lane >> 4) << 3)) * 80 + (((lane >> 3) & 1) << 4));
    const uint32_t awarp = (uint32_t)(wm * 32) * 80;
    const uint32_t bwarp = (uint32_t)(wn * 32) * 80;

    for (int kt = 0; kt < nk; kt++) {
        cp_wait_for(kt, nk);
        __syncthreads();

        uint32_t sb = sbase + (uint32_t)(kt & 3) * OSTAGE;
        #pragma unroll
        for (int kk = 0; kk < 2; kk++) {
            uint32_t sa = sb + awarp + kk * 32 + aoff;
            uint32_t ah[2][4];
            ldm_x4(ah[0], sa);
            ldm_x4(ah[1], sa + 1280);
            uint32_t sB0 = sb + 10240 + bwarp + kk * 32 + boff;
            #pragma unroll
            for (int g = 0; g < 2; g++) {
                uint32_t bh[4];
                ldm_x4(bh, sB0 + g * 1280);
                #pragma unroll
                for (int mt = 0; mt < 2; mt++) {
                    mma16816(acc[mt][2 * g],     ah[mt], &bh[0]);
                    mma16816(acc[mt][2 * g + 1], ah[mt], &bh[2]);
                }
            }
        }
        if (kt + 3 < nk) issue(kt + 3);
    }

    // epilogue: direct store (+bias), cols < 40 only
    const int cbase = wn * 32 + (lane & 3) * 2;
    #pragma unroll
    for (int mt = 0; mt < 2; mt++)
        #pragma unroll
        for (int hh = 0; hh < 2; hh++) {
            int grow = row0 + wm * 32 + mt * 16 + (lane >> 2) + hh * 8;
            if (grow >= M) continue;
            #pragma unroll
            for (int nt = 0; nt < 4; nt++) {
                int c = cbase + nt * 8;
                if (c + 1 < 40) {
                    float2 bv = *(const float2*)&bias[c];
                    float y0 = acc[mt][nt][2 * hh] + bv.x;
                    float y1 = acc[mt][nt][2 * hh + 1] + bv.y;
                    *(float2*)&out[(long long)grow * 40 + c] = make_float2(y0, y1);
                }
            }
        }
}

// ---------------- conversions ----------------
// x fp32 -> fp16
__global__ void conv_x(const float4* __restrict__ src, long long n4,
                       __half* __restrict__ dst)
{
    for (long long i = blockIdx.x * (long long)blockDim.x + threadIdx.x; i < n4;
         i += (long long)gridDim.x * blockDim.x) {
        float4 v = src[i];
        __half2 p0 = __floats2half2_rn(v.x, v.y);
        __half2 p1 = __floats2half2_rn(v.z, v.w);
        *(uint2*)&dst[i * 4] = make_uint2(*(uint32_t*)&p0, *(uint32_t*)&p1);
    }
}

// W [K,256] -> B [n][k] transposed fp16. grid = K blocks, 256 threads.
__global__ void convW(const float* __restrict__ W, __half* __restrict__ b, int K)
{
    int k = blockIdx.x, n = threadIdx.x;
    b[n * K + k] = __float2half(W[k * 256 + n]);
}

// W_out [256,40] -> [64][256] fp16 transposed, zero-padded n>=40. grid=256, 64 thr.
__global__ void convWout(const float* __restrict__ W, __half* __restrict__ b)
{
    int k = blockIdx.x, n = threadIdx.x;
    b[n * 256 + k] = (n < 40) ? __float2half(W[k * 40 + n]) : __ushort_as_half((unsigned short)0);
}

// ---------------- launch ----------------
extern "C" void kernel_launch(void* const* d_in, const int* in_sizes, int n_in,
                              void* d_out, int out_size)
{
    const float* x     = (const float*)d_in[0];
    const float* W_in  = (const float*)d_in[2];
    const float* b_in  = (const float*)d_in[3];
    const float* ln0g  = (const float*)d_in[4];
    const float* ln0b  = (const float*)d_in[5];
    const float* Wv[2] = {(const float*)d_in[10], (const float*)d_in[18]};
    const float* bv[2] = {(const float*)d_in[11], (const float*)d_in[19]};
    const float* lng[2] = {(const float*)d_in[12], (const float*)d_in[20]};
    const float* lnb[2] = {(const float*)d_in[13], (const float*)d_in[21]};
    const float* W_out = (const float*)d_in[22];
    const float* b_out = (const float*)d_in[23];
    float* out = (float*)d_out;

    const int M = in_sizes[0] / 512;
    const int tiles64 = (M + 63) / 64;
    const int tiles128 = (M + 127) / 128;

    __half *pA, *pH, *pB, *pWo;
    cudaGetSymbolAddress((void**)&pA,  g_A);
    cudaGetSymbolAddress((void**)&pH,  g_H);
    cudaGetSymbolAddress((void**)&pB,  g_B);
    cudaGetSymbolAddress((void**)&pWo, g_Wout);

    cudaFuncSetAttribute(gemm_fused<0>, cudaFuncAttributeMaxDynamicSharedMemorySize, DSMEM);
    cudaFuncSetAttribute(gemm_fused<1>, cudaFuncAttributeMaxDynamicSharedMemorySize, DSMEM);
    cudaFuncSetAttribute(out_mma, cudaFuncAttributeMaxDynamicSharedMemorySize, ODSMEM);

    // x -> fp16; W_in -> [256][512] transposed fp16; W_out -> [64][256] fp16
    conv_x<<<2048, 256>>>((const float4*)x, (long long)M * 512 / 4, pA);
    convW<<<512, 256>>>(W_in, pB, 512);
    convWout<<<256, 64>>>(W_out, pWo);
    // h = relu(LN(x @ W_in + b_in)), stored fp16
    gemm_fused<0><<<tiles64, 256, DSMEM>>>(pA, 512, pB, b_in,
                                           pH, ln0g, ln0b, M, 512);

    for (int l = 0; l < 2; l++) {
        convW<<<256, 256>>>(Wv[l], pB, 256);
        // h = LN(0.5*(h@Wv+bv) + 0.5*h), fp16 in place (race-free: own rows)
        gemm_fused<1><<<tiles64, 256, DSMEM>>>(pH, 256, pB, bv[l],
                                               pH, lng[l], lnb[l], M, 256);
    }

    // out = h @ W_out + b_out  (fp16 tensor-core)
    out_mma<<<tiles128, 256, ODSMEM>>>(pH, pWo, b_out, out, M);
}

// round 15
// speedup vs baseline: 3.0894x; 1.2320x over previous
#include <cuda_runtime.h>
#include <cuda_fp16.h>
#include <cstdint>

#define MAXN 100000

// ---------------- device scratch (weights fp16, transposed [n][k]) ----------------
__device__ __half g_Bin[256 * 512];
__device__ __half g_Bv0[256 * 256];
__device__ __half g_Bv1[256 * 256];
__device__ __half g_Wo[64 * 256];      // W_out, n padded to 64

// ---------------- PTX helpers (compute_103-safe) ----------------
__device__ __forceinline__ uint32_t smem_u32(const void* p) {
    uint32_t a;
    asm("{ .reg .u64 t; cvta.to.shared.u64 t, %1; cvt.u32.u64 %0, t; }" : "=r"(a) : "l"(p));
    return a;
}
__device__ __forceinline__ void cp16(uint32_t dst, const void* src) {
    asm volatile("cp.async.cg.shared.global [%0], [%1], 16;" :: "r"(dst), "l"(src));
}
__device__ __forceinline__ void cp_commit() {
    asm volatile("cp.async.commit_group;" ::: "memory");
}
__device__ __forceinline__ void cp_wait0() {
    asm volatile("cp.async.wait_group 0;" ::: "memory");
}
__device__ __forceinline__ void cp_wait1() {
    asm volatile("cp.async.wait_group 1;" ::: "memory");
}
__device__ __forceinline__ void ldm_x4(uint32_t* r, uint32_t addr) {
    asm volatile("ldmatrix.sync.aligned.m8n8.x4.shared.b16 {%0,%1,%2,%3}, [%4];"
        : "=r"(r[0]), "=r"(r[1]), "=r"(r[2]), "=r"(r[3]) : "r"(addr));
}
__device__ __forceinline__ void mma16816(float* c, const uint32_t* a, const uint32_t* b) {
    asm volatile("mma.sync.aligned.m16n8k16.row.col.f32.f16.f16.f32 "
        "{%0,%1,%2,%3}, {%4,%5,%6,%7}, {%8,%9}, {%0,%1,%2,%3};"
        : "+f"(c[0]), "+f"(c[1]), "+f"(c[2]), "+f"(c[3])
        : "r"(a[0]), "r"(a[1]), "r"(a[2]), "r"(a[3]), "r"(b[0]), "r"(b[1]));
}

// ---------------- SMEM map (dynamic, per CTA) ----------------
// [0, 57344)       phase-1 stages (x2): Afp32 @+0 (8192 = 64 rows x 128B), B @+8192 (20480)
//                  phases 2/3 reuse [0, 61440) as 3 x 20480 B stages
//                  phase 4 reuses [0, 40960) as 8 x 5120 Wout tiles
// [57344, 62464)   phase-1 fp16 A tile (64 rows x 80B), single buffer
// [62464, 103424)  Ares: resident h, 8 tiles x 5120 (ldmatrix stage layout)
#define P1_STAGE 28672
#define A16_OFF  57344
#define ARES_OFF 62464
#define DSMEM    103424

// ---------------- fused LN epilogue: bias (+residual) + LN (+relu) -> Ares ----------
// RESID=0: h = relu(LN(C+bias));  RESID=1: h = LN(0.5*(C+bias) + 0.5*h_prev)
// Caller must __syncthreads() before (Ares read hazard) and after (Ares write hazard).
template<int RESID>
__device__ __forceinline__ void epilogue_ln(
    float (&acc)[2][8][4], char* dsm, float2 (*red)[4],
    const float* __restrict__ bias,
    const float* __restrict__ lng, const float* __restrict__ lnb,
    int wm, int wn, int lane)
{
    const int cbase = wn * 64 + (lane & 3) * 2;
    #pragma unroll
    for (int mt = 0; mt < 2; mt++)
        #pragma unroll
        for (int hh = 0; hh < 2; hh++) {
            int row = wm * 32 + mt * 16 + (lane >> 2) + hh * 8;
            float s = 0.f, s2 = 0.f;
            #pragma unroll
            for (int nt = 0; nt < 8; nt++) {
                int c = cbase + nt * 8;
                float2 bsv = *(const float2*)&bias[c];
                float x0 = acc[mt][nt][2 * hh], x1 = acc[mt][nt][2 * hh + 1];
                if (RESID) {
                    uint32_t hp = *(const uint32_t*)(dsm + ARES_OFF +
                        (c >> 5) * 5120 + row * 80 + (c & 31) * 2);
                    __half2 hv = *(__half2*)&hp;
                    x0 = 0.5f * (x0 + bsv.x + __half2float(hv.x));
                    x1 = 0.5f * (x1 + bsv.y + __half2float(hv.y));
                } else {
                    x0 += bsv.x; x1 += bsv.y;
                }
                acc[mt][nt][2 * hh] = x0;
                acc[mt][nt][2 * hh + 1] = x1;
                s += x0 + x1;
                s2 += x0 * x0 + x1 * x1;
            }
            s  += __shfl_xor_sync(0xffffffffu, s, 1);
            s  += __shfl_xor_sync(0xffffffffu, s, 2);
            s2 += __shfl_xor_sync(0xffffffffu, s2, 1);
            s2 += __shfl_xor_sync(0xffffffffu, s2, 2);
            if ((lane & 3) == 0) red[row][wn] = make_float2(s, s2);
        }
    __syncthreads();

    #pragma unroll
    for (int mt = 0; mt < 2; mt++)
        #pragma unroll
        for (int hh = 0; hh < 2; hh++) {
            int row = wm * 32 + mt * 16 + (lane >> 2) + hh * 8;
            float2 r0 = red[row][0], r1 = red[row][1], r2 = red[row][2], r3 = red[row][3];
            float s  = r0.x + r1.x + r2.x + r3.x;
            float s2 = r0.y + r1.y + r2.y + r3.y;
            float mu = s * (1.f / 256.f);
            float var = s2 * (1.f / 256.f) - mu * mu;
            float rstd = rsqrtf(var + 1e-5f);
            #pragma unroll
            for (int nt = 0; nt < 8; nt++) {
                int c = cbase + nt * 8;
                float2 gv = *(const float2*)&lng[c];
                float2 bv = *(const float2*)&lnb[c];
                float y0 = gv.x * (acc[mt][nt][2 * hh] - mu) * rstd + bv.x;
                float y1 = gv.y * (acc[mt][nt][2 * hh + 1] - mu) * rstd + bv.y;
                if (!RESID) { y0 = fmaxf(y0, 0.f); y1 = fmaxf(y1, 0.f); }
                __half h0 = __float2half(y0);
                __half h1 = __float2half(y1);
                uint32_t hp = (uint32_t)__half_as_ushort(h0) |
                              ((uint32_t)__half_as_ushort(h1) << 16);
                *(uint32_t*)(dsm + ARES_OFF + (c >> 5) * 5120 + row * 80 + (c & 31) * 2) = hp;
            }
        }
}

// ============ mega kernel: whole network for 64 rows per CTA ============
// phase 1: x[64,512] fp32 -> per-tile fp16 -> @Bin^T, LN+ReLU -> Ares (SMEM)
// phase 2: Ares @ Bv0^T, LN+resid -> Ares
// phase 3: Ares @ Bv1^T, LN+resid -> Ares
// phase 4: Ares @ Wo^T (+b_out) -> out[64,40] fp32
// 256 threads (8 warps: 2m x 4n, 32x64 warp tile), 2 CTAs/SM.
__global__ void __launch_bounds__(256, 2) mega(
    const float* __restrict__ X,
    const __half* __restrict__ Bin,
    const __half* __restrict__ Bv0, const __half* __restrict__ Bv1,
    const __half* __restrict__ Wo,
    const float* __restrict__ b_in,
    const float* __restrict__ bv0, const float* __restrict__ bv1,
    const float* __restrict__ b_out,
    const float* __restrict__ g0, const float* __restrict__ e0,
    const float* __restrict__ g1, const float* __restrict__ e1,
    const float* __restrict__ g2, const float* __restrict__ e2,
    float* __restrict__ out, int M)
{
    extern __shared__ char dsm[];
    __shared__ float2 red[64][4];
    const int tid = threadIdx.x;
    const int lane = tid & 31, wid = tid >> 5;
    const int wm = wid >> 2, wn = wid & 3;        // 2 x 4 warp grid
    const int row0 = blockIdx.x * 64;

    const uint32_t pipe = smem_u32(dsm);
    const uint32_t A16  = pipe + A16_OFF;
    const uint32_t Ares = pipe + ARES_OFF;

    const uint32_t aoff = (uint32_t)((lane & 15) * 80 + (lane >> 4) * 16);
    const uint32_t boff = (uint32_t)(((lane & 7) + ((lane >> 4) << 3)) * 80 + (((lane >> 3) & 1) << 4));
    const uint32_t awarp = (uint32_t)(wm * 32) * 80;
    const uint32_t bwarp = (uint32_t)(wn * 64) * 80;

    float acc[2][8][4];
    #pragma unroll
    for (int a = 0; a < 2; a++)
        #pragma unroll
        for (int b = 0; b < 8; b++)
            #pragma unroll
            for (int c = 0; c < 4; c++) acc[a][b][c] = 0.f;

    // ================= Phase 1: x @ Bin^T (K=512, nk=16, 2-stage) =================
    {
        // 6 x 16B chunks/thread/stage: A-fp32 512 chunks (i<2), B 1024 chunks (i>=2)
        const char* gP[6];
        uint32_t sO[6];
        #pragma unroll
        for (int i = 0; i < 6; i++) {
            int cid = tid + i * 256;
            if (cid < 512) {                 // A fp32: 64 rows x 8 segs of 16B (128B/row)
                int r = cid >> 3, seg = cid & 7;
                int ar = min(row0 + r, M - 1);
                gP[i] = (const char*)(X + (long long)ar * 512 + seg * 4);
                sO[i] = (uint32_t)(r * 128 + seg * 16);
            } else {                         // B fp16: 256 rows x 4 segs (80B stride)
                int c2 = cid - 512;
                int r = c2 >> 2, seg = c2 & 3;
                gP[i] = (const char*)(Bin + (long long)r * 512 + seg * 8);
                sO[i] = 8192u + (uint32_t)(r * 80 + seg * 16);
            }
        }
        auto issue1 = [&](int kt) {
            uint32_t sb = pipe + (uint32_t)(kt & 1) * P1_STAGE;
            #pragma unroll
            for (int i = 0; i < 6; i++)
                cp16(sb + sO[i], gP[i] + (long long)kt * (i < 2 ? 128 : 64));
            cp_commit();
        };

        issue1(0);
        for (int kt = 0; kt < 16; kt++) {
            cp_wait0();
            __syncthreads();
            // convert fp32 A tile -> fp16 A16 (single buffer; all done with it by sync above)
            {
                const float* src = (const float*)(dsm + (kt & 1) * P1_STAGE);
                int r = tid >> 2, ks = (tid & 3) * 8;
                float4 v0 = *(const float4*)(src + r * 32 + ks);
                float4 v1 = *(const float4*)(src + r * 32 + ks + 4);
                __half2 p0 = __floats2half2_rn(v0.x, v0.y);
                __half2 p1 = __floats2half2_rn(v0.z, v0.w);
                __half2 p2 = __floats2half2_rn(v1.x, v1.y);
                __half2 p3 = __floats2half2_rn(v1.z, v1.w);
                *(uint4*)(dsm + A16_OFF + r * 80 + ks * 2) =
                    make_uint4(*(uint32_t*)&p0, *(uint32_t*)&p1,
                               *(uint32_t*)&p2, *(uint32_t*)&p3);
            }
            __syncthreads();
            // prefetch next stage: buf (kt+1)&1 fully consumed at iter kt-1 (all passed sync)
            if (kt + 1 < 16) issue1(kt + 1);
            // compute from A16 + B buf kt&1
            uint32_t sbB = pipe + (uint32_t)(kt & 1) * P1_STAGE + 8192;
            #pragma unroll
            for (int kk = 0; kk < 2; kk++) {
                uint32_t sa = A16 + awarp + kk * 32 + aoff;
                uint32_t ah[2][4];
                ldm_x4(ah[0], sa);
                ldm_x4(ah[1], sa + 1280);
                uint32_t sB0 = sbB + bwarp + kk * 32 + boff;
                #pragma unroll
                for (int g = 0; g < 4; g++) {
                    uint32_t bh[4];
                    ldm_x4(bh, sB0 + g * 1280);
                    #pragma unroll
                    for (int mt = 0; mt < 2; mt++) {
                        mma16816(acc[mt][2 * g],     ah[mt], &bh[0]);
                        mma16816(acc[mt][2 * g + 1], ah[mt], &bh[2]);
                    }
                }
            }
        }
    }
    __syncthreads();
    epilogue_ln<0>(acc, dsm, red, b_in, g0, e0, wm, wn, lane);
    __syncthreads();

    // ================= Phases 2/3: h @ Bv^T (K=256, nk=8, 3-stage B-only) ==========
    #pragma unroll 1
    for (int l = 0; l < 2; l++) {
        const __half* B = (l == 0) ? Bv0 : Bv1;
        const float* bias = (l == 0) ? bv0 : bv1;
        const float* lg = (l == 0) ? g1 : g2;
        const float* lb = (l == 0) ? e1 : e2;

        #pragma unroll
        for (int a = 0; a < 2; a++)
            #pragma unroll
            for (int b = 0; b < 8; b++)
                #pragma unroll
                for (int c = 0; c < 4; c++) acc[a][b][c] = 0.f;

        const __half* gP[4];
        uint32_t sO[4];
        #pragma unroll
        for (int i = 0; i < 4; i++) {
            int cid = tid + i * 256;            // 1024 B chunks
            int r = cid >> 2, seg = cid & 3;
            gP[i] = B + (long long)r * 256 + seg * 8;
            sO[i] = (uint32_t)(r * 80 + seg * 16);
        }
        auto issueB = [&](int kt) {
            uint32_t sb = pipe + (uint32_t)(kt % 3) * 20480;
            #pragma unroll
            for (int i = 0; i < 4; i++) cp16(sb + sO[i], gP[i] + (long long)kt * 32);
            cp_commit();
        };

        issueB(0);
        issueB(1);
        for (int kt = 0; kt < 8; kt++) {
            if (kt < 7) cp_wait1(); else cp_wait0();   // issued = min(kt+2,8); pending = issued-(kt+1)
            __syncthreads();
            uint32_t sbB = pipe + (uint32_t)(kt % 3) * 20480;
            #pragma unroll
            for (int kk = 0; kk < 2; kk++) {
                uint32_t sa = Ares + kt * 5120 + awarp + kk * 32 + aoff;
                uint32_t ah[2][4];
                ldm_x4(ah[0], sa);
                ldm_x4(ah[1], sa + 1280);
                uint32_t sB0 = sbB + bwarp + kk * 32 + boff;
                #pragma unroll
                for (int g = 0; g < 4; g++) {
                    uint32_t bh[4];
                    ldm_x4(bh, sB0 + g * 1280);
                    #pragma unroll
                    for (int mt = 0; mt < 2; mt++) {
                        mma16816(acc[mt][2 * g],     ah[mt], &bh[0]);
                        mma16816(acc[mt][2 * g + 1], ah[mt], &bh[2]);
                    }
                }
            }
            // stage (kt+2)%3 == (kt-1)%3: consumed at iter kt-1, all passed this barrier
            if (kt + 2 < 8) issueB(kt + 2);
        }
        __syncthreads();     // all Ares mainloop reads done before epilogue overwrites
        epilogue_ln<1>(acc, dsm, red, bias, lg, lb, wm, wn, lane);
        __syncthreads();
    }

    // ================= Phase 4: out = h @ Wo^T + b_out (Wout fully resident) =======
    {
        // load ALL of Wo: 8 tiles x (64 rows x 80B) = 40960 B, one group
        #pragma unroll
        for (int i = 0; i < 8; i++) {
            int cid = tid + i * 256;            // 2048 chunks
            int t = cid >> 8;
            int c2 = cid & 255;
            int r = c2 >> 2, seg = c2 & 3;
            cp16(pipe + t * 5120 + (uint32_t)(r * 80 + seg * 16),
                 Wo + (long long)r * 256 + t * 32 + seg * 8);
        }
        cp_commit();
        cp_wait0();
        __syncthreads();

        float facc[2][2][4] = {};
        const uint32_t bwarp4 = (uint32_t)(wn * 16) * 80;
        for (int kt = 0; kt < 8; kt++) {
            #pragma unroll
            for (int kk = 0; kk < 2; kk++) {
                uint32_t sa = Ares + kt * 5120 + awarp + kk * 32 + aoff;
                uint32_t ah[2][4];
                ldm_x4(ah[0], sa);
                ldm_x4(ah[1], sa + 1280);
                uint32_t bh[4];
                ldm_x4(bh, pipe + kt * 5120 + bwarp4 + kk * 32 + boff);
                #pragma unroll
                for (int mt = 0; mt < 2; mt++) {
                    mma16816(facc[mt][0], ah[mt], &bh[0]);
                    mma16816(facc[mt][1], ah[mt], &bh[2]);
                }
            }
        }

        const int cb4 = wn * 16 + (lane & 3) * 2;
        #pragma unroll
        for (int mt = 0; mt < 2; mt++)
            #pragma unroll
            for (int hh = 0; hh < 2; hh++) {
                int grow = row0 + wm * 32 + mt * 16 + (lane >> 2) + hh * 8;
                if (grow >= M) continue;
                #pragma unroll
                for (int nt = 0; nt < 2; nt++) {
                    int c = cb4 + nt * 8;
                    if (c + 1 < 40) {
                        float2 bv = *(const float2*)&b_out[c];
                        float y0 = facc[mt][nt][2 * hh] + bv.x;
                        float y1 = facc[mt][nt][2 * hh + 1] + bv.y;
                        *(float2*)&out[(long long)grow * 40 + c] = make_float2(y0, y1);
                    }
                }
            }
    }
}

// ---------------- one-shot weight conversion (all weights, fp16 transposed) --------
__global__ void convAll(const float* __restrict__ W_in,
                        const float* __restrict__ Wv0, const float* __restrict__ Wv1,
                        const float* __restrict__ W_out,
                        __half* __restrict__ Bin,
                        __half* __restrict__ Bv0, __half* __restrict__ Bv1,
                        __half* __restrict__ Wo)
{
    int idx = blockIdx.x * 256 + threadIdx.x;
    if (blockIdx.x < 512) {                       // Bin [256][512]
        int n = idx >> 9, k = idx & 511;
        Bin[idx] = __float2half(W_in[k * 256 + n]);
    } else if (blockIdx.x < 768) {                // Bv0 [256][256]
        int j = idx - 131072;
        int n = j >> 8, k = j & 255;
        Bv0[j] = __float2half(Wv0[k * 256 + n]);
    } else if (blockIdx.x < 1024) {               // Bv1 [256][256]
        int j = idx - 196608;
        int n = j >> 8, k = j & 255;
        Bv1[j] = __float2half(Wv1[k * 256 + n]);
    } else {                                      // Wo [64][256], zero-pad n>=40
        int j = idx - 262144;
        int n = j >> 8, k = j & 255;
        Wo[j] = (n < 40) ? __float2half(W_out[k * 40 + n]) : __ushort_as_half((unsigned short)0);
    }
}

// ---------------- launch ----------------
extern "C" void kernel_launch(void* const* d_in, const int* in_sizes, int n_in,
                              void* d_out, int out_size)
{
    const float* x     = (const float*)d_in[0];
    const float* W_in  = (const float*)d_in[2];
    const float* b_in  = (const float*)d_in[3];
    const float* ln0g  = (const float*)d_in[4];
    const float* ln0b  = (const float*)d_in[5];
    const float* Wv0   = (const float*)d_in[10];
    const float* bv0   = (const float*)d_in[11];
    const float* ln1g  = (const float*)d_in[12];
    const float* ln1b  = (const float*)d_in[13];
    const float* Wv1   = (const float*)d_in[18];
    const float* bv1   = (const float*)d_in[19];
    const float* ln2g  = (const float*)d_in[20];
    const float* ln2b  = (const float*)d_in[21];
    const float* W_out = (const float*)d_in[22];
    const float* b_out = (const float*)d_in[23];
    float* out = (float*)d_out;

    const int M = in_sizes[0] / 512;
    const int tiles64 = (M + 63) / 64;

    __half *pBin, *pBv0, *pBv1, *pWo;
    cudaGetSymbolAddress((void**)&pBin, g_Bin);
    cudaGetSymbolAddress((void**)&pBv0, g_Bv0);
    cudaGetSymbolAddress((void**)&pBv1, g_Bv1);
    cudaGetSymbolAddress((void**)&pWo,  g_Wo);

    cudaFuncSetAttribute(mega, cudaFuncAttributeMaxDynamicSharedMemorySize, DSMEM);

    convAll<<<1088, 256>>>(W_in, Wv0, Wv1, W_out, pBin, pBv0, pBv1, pWo);
    mega<<<tiles64, 256, DSMEM>>>(x, pBin, pBv0, pBv1, pWo,
                                  b_in, bv0, bv1, b_out,
                                  ln0g, ln0b, ln1g, ln1b, ln2g, ln2b,
                                  out, M);
}

// round 16
// speedup vs baseline: 3.4072x; 1.1028x over previous
#include <cuda_runtime.h>
#include <cuda_fp16.h>
#include <cstdint>

#define MAXN 100000

// ---------------- device scratch (weights fp16, transposed [n][k]) ----------------
__device__ __half g_Bin[256 * 512];
__device__ __half g_Bv0[256 * 256];
__device__ __half g_Bv1[256 * 256];
__device__ __half g_Wo[64 * 256];      // W_out, n padded to 64

// ---------------- PTX helpers (compute_103-safe) ----------------
__device__ __forceinline__ uint32_t smem_u32(const void* p) {
    uint32_t a;
    asm("{ .reg .u64 t; cvta.to.shared.u64 t, %1; cvt.u32.u64 %0, t; }" : "=r"(a) : "l"(p));
    return a;
}
__device__ __forceinline__ void cp16(uint32_t dst, const void* src) {
    asm volatile("cp.async.cg.shared.global [%0], [%1], 16;" :: "r"(dst), "l"(src));
}
__device__ __forceinline__ void cp_commit() {
    asm volatile("cp.async.commit_group;" ::: "memory");
}
__device__ __forceinline__ void cp_wait0() {
    asm volatile("cp.async.wait_group 0;" ::: "memory");
}
__device__ __forceinline__ void cp_wait1() {
    asm volatile("cp.async.wait_group 1;" ::: "memory");
}
__device__ __forceinline__ void ldm_x4(uint32_t* r, uint32_t addr) {
    asm volatile("ldmatrix.sync.aligned.m8n8.x4.shared.b16 {%0,%1,%2,%3}, [%4];"
        : "=r"(r[0]), "=r"(r[1]), "=r"(r[2]), "=r"(r[3]) : "r"(addr));
}
__device__ __forceinline__ void mma16816(float* c, const uint32_t* a, const uint32_t* b) {
    asm volatile("mma.sync.aligned.m16n8k16.row.col.f32.f16.f16.f32 "
        "{%0,%1,%2,%3}, {%4,%5,%6,%7}, {%8,%9}, {%0,%1,%2,%3};"
        : "+f"(c[0]), "+f"(c[1]), "+f"(c[2]), "+f"(c[3])
        : "r"(a[0]), "r"(a[1]), "r"(a[2]), "r"(a[3]), "r"(b[0]), "r"(b[1]));
}

// ---------------- SMEM map (dynamic, per CTA) ----------------
// [0, 61440)        B ring: 3 stages x 20480 (phases 1-3); phase 4: 8 x 5120 Wo tiles
// [61440, 71680)    A16: phase-1 fp16 A tile, double buffered (2 x 5120)
// [71680, 112640)   Ares: resident h, 8 tiles x 5120 (ldmatrix stage layout)
#define BSTAGE   20480
#define A16_OFF  61440
#define ARES_OFF 71680
#define DSMEM    112640

// ---------------- fused LN epilogue: bias (+residual) + LN (+relu) -> Ares ----------
// RESID=0: h = relu(LN(C+bias));  RESID=1: h = LN(0.5*(C+bias) + 0.5*h_prev)
// Caller must __syncthreads() before (Ares read hazard) and after (Ares write hazard).
template<int RESID>
__device__ __forceinline__ void epilogue_ln(
    float (&acc)[2][8][4], char* dsm, float2 (*red)[4],
    const float* __restrict__ bias,
    const float* __restrict__ lng, const float* __restrict__ lnb,
    int wm, int wn, int lane)
{
    const int cbase = wn * 64 + (lane & 3) * 2;
    #pragma unroll
    for (int mt = 0; mt < 2; mt++)
        #pragma unroll
        for (int hh = 0; hh < 2; hh++) {
            int row = wm * 32 + mt * 16 + (lane >> 2) + hh * 8;
            float s = 0.f, s2 = 0.f;
            #pragma unroll
            for (int nt = 0; nt < 8; nt++) {
                int c = cbase + nt * 8;
                float2 bsv = *(const float2*)&bias[c];
                float x0 = acc[mt][nt][2 * hh], x1 = acc[mt][nt][2 * hh + 1];
                if (RESID) {
                    uint32_t hp = *(const uint32_t*)(dsm + ARES_OFF +
                        (c >> 5) * 5120 + row * 80 + (c & 31) * 2);
                    __half2 hv = *(__half2*)&hp;
                    x0 = 0.5f * (x0 + bsv.x + __half2float(hv.x));
                    x1 = 0.5f * (x1 + bsv.y + __half2float(hv.y));
                } else {
                    x0 += bsv.x; x1 += bsv.y;
                }
                acc[mt][nt][2 * hh] = x0;
                acc[mt][nt][2 * hh + 1] = x1;
                s += x0 + x1;
                s2 += x0 * x0 + x1 * x1;
            }
            s  += __shfl_xor_sync(0xffffffffu, s, 1);
            s  += __shfl_xor_sync(0xffffffffu, s, 2);
            s2 += __shfl_xor_sync(0xffffffffu, s2, 1);
            s2 += __shfl_xor_sync(0xffffffffu, s2, 2);
            if ((lane & 3) == 0) red[row][wn] = make_float2(s, s2);
        }
    __syncthreads();

    #pragma unroll
    for (int mt = 0; mt < 2; mt++)
        #pragma unroll
        for (int hh = 0; hh < 2; hh++) {
            int row = wm * 32 + mt * 16 + (lane >> 2) + hh * 8;
            float2 r0 = red[row][0], r1 = red[row][1], r2 = red[row][2], r3 = red[row][3];
            float s  = r0.x + r1.x + r2.x + r3.x;
            float s2 = r0.y + r1.y + r2.y + r3.y;
            float mu = s * (1.f / 256.f);
            float var = s2 * (1.f / 256.f) - mu * mu;
            float rstd = rsqrtf(var + 1e-5f);
            #pragma unroll
            for (int nt = 0; nt < 8; nt++) {
                int c = cbase + nt * 8;
                float2 gv = *(const float2*)&lng[c];
                float2 bv = *(const float2*)&lnb[c];
                float y0 = gv.x * (acc[mt][nt][2 * hh] - mu) * rstd + bv.x;
                float y1 = gv.y * (acc[mt][nt][2 * hh + 1] - mu) * rstd + bv.y;
                if (!RESID) { y0 = fmaxf(y0, 0.f); y1 = fmaxf(y1, 0.f); }
                __half h0 = __float2half(y0);
                __half h1 = __float2half(y1);
                uint32_t hp = (uint32_t)__half_as_ushort(h0) |
                              ((uint32_t)__half_as_ushort(h1) << 16);
                *(uint32_t*)(dsm + ARES_OFF + (c >> 5) * 5120 + row * 80 + (c & 31) * 2) = hp;
            }
        }
}

// ============ mega kernel: whole network for 64 rows per CTA ============
// phase 1: x[64,512] fp32 (register-direct LDG -> fp16 A16 dbl-buf) @ Bin^T, LN+ReLU -> Ares
// phase 2: Ares @ Bv0^T, LN+resid -> Ares
// phase 3: Ares @ Bv1^T, LN+resid -> Ares
// phase 4: Ares @ Wo^T (+b_out) -> out[64,40] fp32
// 256 threads (8 warps: 2m x 4n, 32x64 warp tile), 2 CTAs/SM.
__global__ void __launch_bounds__(256, 2) mega(
    const float* __restrict__ X,
    const __half* __restrict__ Bin,
    const __half* __restrict__ Bv0, const __half* __restrict__ Bv1,
    const __half* __restrict__ Wo,
    const float* __restrict__ b_in,
    const float* __restrict__ bv0, const float* __restrict__ bv1,
    const float* __restrict__ b_out,
    const float* __restrict__ g0, const float* __restrict__ e0,
    const float* __restrict__ g1, const float* __restrict__ e1,
    const float* __restrict__ g2, const float* __restrict__ e2,
    float* __restrict__ out, int M)
{
    extern __shared__ char dsm[];
    __shared__ float2 red[64][4];
    const int tid = threadIdx.x;
    const int lane = tid & 31, wid = tid >> 5;
    const int wm = wid >> 2, wn = wid & 3;        // 2 x 4 warp grid
    const int row0 = blockIdx.x * 64;

    const uint32_t pipe = smem_u32(dsm);
    const uint32_t A16  = pipe + A16_OFF;
    const uint32_t Ares = pipe + ARES_OFF;

    const uint32_t aoff = (uint32_t)((lane & 15) * 80 + (lane >> 4) * 16);
    const uint32_t boff = (uint32_t)(((lane & 7) + ((lane >> 4) << 3)) * 80 + (((lane >> 3) & 1) << 4));
    const uint32_t awarp = (uint32_t)(wm * 32) * 80;
    const uint32_t bwarp = (uint32_t)(wn * 64) * 80;

    float acc[2][8][4];
    #pragma unroll
    for (int a = 0; a < 2; a++)
        #pragma unroll
        for (int b = 0; b < 8; b++)
            #pragma unroll
            for (int c = 0; c < 4; c++) acc[a][b][c] = 0.f;

    // ============== Phase 1: x @ Bin^T (K=512, nk=16) ==============
    // A: register-direct LDG + in-reg fp32->fp16, double-buffered A16 (no A in cp ring).
    // B: 3-stage cp.async ring, 2-deep prefetch (verified scheme from phases 2/3).
    {
        // per-thread A assignment: 2 chunks of 4 floats (16B LDG)
        const float* xP[2];
        uint32_t cvD[2];
        #pragma unroll
        for (int i = 0; i < 2; i++) {
            int cid = tid + i * 256;
            int r = cid >> 3, seg = cid & 7;
            int ar = min(row0 + r, M - 1);
            xP[i] = X + (long long)ar * 512 + seg * 4;
            cvD[i] = (uint32_t)(r * 80 + seg * 8);   // fp16 dest: 4 halves = 8B
        }
        // B ring assignment: 1024 chunks -> 4/thread
        const __half* gB[4];
        uint32_t sB[4];
        #pragma unroll
        for (int i = 0; i < 4; i++) {
            int cid = tid + i * 256;
            int r = cid >> 2, seg = cid & 3;
            gB[i] = Bin + (long long)r * 512 + seg * 8;
            sB[i] = (uint32_t)(r * 80 + seg * 16);
        }
        auto issueB = [&](int kt) {
            uint32_t sb = pipe + (uint32_t)(kt % 3) * BSTAGE;
            #pragma unroll
            for (int i = 0; i < 4; i++) cp16(sb + sB[i], gB[i] + (long long)kt * 32);
            cp_commit();
        };

        float4 xr[2];
        xr[0] = *(const float4*)xP[0];
        xr[1] = *(const float4*)xP[1];
        issueB(0);
        issueB(1);

        for (int kt = 0; kt < 16; kt++) {
            // convert current x regs -> A16[kt&1]
            uint32_t abuf = A16 - pipe + (uint32_t)(kt & 1) * 5120;
            #pragma unroll
            for (int i = 0; i < 2; i++) {
                __half2 p0 = __floats2half2_rn(xr[i].x, xr[i].y);
                __half2 p1 = __floats2half2_rn(xr[i].z, xr[i].w);
                *(uint2*)(dsm + abuf + cvD[i]) = make_uint2(*(uint32_t*)&p0, *(uint32_t*)&p1);
            }
            // prefetch next x tile into regs (LDG overlaps this iteration's mma)
            if (kt + 1 < 16) {
                xr[0] = *(const float4*)(xP[0] + (kt + 1) * 32);
                xr[1] = *(const float4*)(xP[1] + (kt + 1) * 32);
            }
            // B wait: issued = min(kt+2,16); pending allowed = issued-(kt+1)
            if (kt < 15) cp_wait1(); else cp_wait0();
            __syncthreads();   // A16[kt&1] writes + B stage kt%3 visible to all

            uint32_t sbB = pipe + (uint32_t)(kt % 3) * BSTAGE;
            uint32_t saB = pipe + abuf;
            #pragma unroll
            for (int kk = 0; kk < 2; kk++) {
                uint32_t sa = saB + awarp + kk * 32 + aoff;
                uint32_t ah[2][4];
                ldm_x4(ah[0], sa);
                ldm_x4(ah[1], sa + 1280);
                uint32_t sB0 = sbB + bwarp + kk * 32 + boff;
                #pragma unroll
                for (int g = 0; g < 4; g++) {
                    uint32_t bh[4];
                    ldm_x4(bh, sB0 + g * 1280);
                    #pragma unroll
                    for (int mt = 0; mt < 2; mt++) {
                        mma16816(acc[mt][2 * g],     ah[mt], &bh[0]);
                        mma16816(acc[mt][2 * g + 1], ah[mt], &bh[2]);
                    }
                }
            }
            // stage (kt+2)%3 == (kt-1)%3: its readers all passed THIS iteration's barrier
            if (kt + 2 < 16) issueB(kt + 2);
        }
    }
    __syncthreads();
    epilogue_ln<0>(acc, dsm, red, b_in, g0, e0, wm, wn, lane);
    __syncthreads();

    // ================= Phases 2/3: h @ Bv^T (K=256, nk=8, 3-stage B-only) ==========
    #pragma unroll 1
    for (int l = 0; l < 2; l++) {
        const __half* B = (l == 0) ? Bv0 : Bv1;
        const float* bias = (l == 0) ? bv0 : bv1;
        const float* lg = (l == 0) ? g1 : g2;
        const float* lb = (l == 0) ? e1 : e2;

        #pragma unroll
        for (int a = 0; a < 2; a++)
            #pragma unroll
            for (int b = 0; b < 8; b++)
                #pragma unroll
                for (int c = 0; c < 4; c++) acc[a][b][c] = 0.f;

        const __half* gP[4];
        uint32_t sO[4];
        #pragma unroll
        for (int i = 0; i < 4; i++) {
            int cid = tid + i * 256;            // 1024 B chunks
            int r = cid >> 2, seg = cid & 3;
            gP[i] = B + (long long)r * 256 + seg * 8;
            sO[i] = (uint32_t)(r * 80 + seg * 16);
        }
        auto issueB = [&](int kt) {
            uint32_t sb = pipe + (uint32_t)(kt % 3) * BSTAGE;
            #pragma unroll
            for (int i = 0; i < 4; i++) cp16(sb + sO[i], gP[i] + (long long)kt * 32);
            cp_commit();
        };

        issueB(0);
        issueB(1);
        for (int kt = 0; kt < 8; kt++) {
            if (kt < 7) cp_wait1(); else cp_wait0();   // issued = min(kt+2,8); pending = issued-(kt+1)
            __syncthreads();
            uint32_t sbB = pipe + (uint32_t)(kt % 3) * BSTAGE;
            #pragma unroll
            for (int kk = 0; kk < 2; kk++) {
                uint32_t sa = Ares + kt * 5120 + awarp + kk * 32 + aoff;
                uint32_t ah[2][4];
                ldm_x4(ah[0], sa);
                ldm_x4(ah[1], sa + 1280);
                uint32_t sB0 = sbB + bwarp + kk * 32 + boff;
                #pragma unroll
                for (int g = 0; g < 4; g++) {
                    uint32_t bh[4];
                    ldm_x4(bh, sB0 + g * 1280);
                    #pragma unroll
                    for (int mt = 0; mt < 2; mt++) {
                        mma16816(acc[mt][2 * g],     ah[mt], &bh[0]);
                        mma16816(acc[mt][2 * g + 1], ah[mt], &bh[2]);
                    }
                }
            }
            // stage (kt+2)%3 == (kt-1)%3: consumed at iter kt-1, all passed this barrier
            if (kt + 2 < 8) issueB(kt + 2);
        }
        __syncthreads();     // all Ares mainloop reads done before epilogue overwrites
        epilogue_ln<1>(acc, dsm, red, bias, lg, lb, wm, wn, lane);
        __syncthreads();
    }

    // ================= Phase 4: out = h @ Wo^T + b_out (Wout fully resident) =======
    {
        // load ALL of Wo: 8 tiles x (64 rows x 80B) = 40960 B, one group
        #pragma unroll
        for (int i = 0; i < 8; i++) {
            int cid = tid + i * 256;            // 2048 chunks
            int t = cid >> 8;
            int c2 = cid & 255;
            int r = c2 >> 2, seg = c2 & 3;
            cp16(pipe + t * 5120 + (uint32_t)(r * 80 + seg * 16),
                 Wo + (long long)r * 256 + t * 32 + seg * 8);
        }
        cp_commit();
        cp_wait0();
        __syncthreads();

        float facc[2][2][4] = {};
        const uint32_t bwarp4 = (uint32_t)(wn * 16) * 80;
        for (int kt = 0; kt < 8; kt++) {
            #pragma unroll
            for (int kk = 0; kk < 2; kk++) {
                uint32_t sa = Ares + kt * 5120 + awarp + kk * 32 + aoff;
                uint32_t ah[2][4];
                ldm_x4(ah[0], sa);
                ldm_x4(ah[1], sa + 1280);
                uint32_t bh[4];
                ldm_x4(bh, pipe + kt * 5120 + bwarp4 + kk * 32 + boff);
                #pragma unroll
                for (int mt = 0; mt < 2; mt++) {
                    mma16816(facc[mt][0], ah[mt], &bh[0]);
                    mma16816(facc[mt][1], ah[mt], &bh[2]);
                }
            }
        }

        const int cb4 = wn * 16 + (lane & 3) * 2;
        #pragma unroll
        for (int mt = 0; mt < 2; mt++)
            #pragma unroll
            for (int hh = 0; hh < 2; hh++) {
                int grow = row0 + wm * 32 + mt * 16 + (lane >> 2) + hh * 8;
                if (grow >= M) continue;
                #pragma unroll
                for (int nt = 0; nt < 2; nt++) {
                    int c = cb4 + nt * 8;
                    if (c + 1 < 40) {
                        float2 bv = *(const float2*)&b_out[c];
                        float y0 = facc[mt][nt][2 * hh] + bv.x;
                        float y1 = facc[mt][nt][2 * hh + 1] + bv.y;
                        *(float2*)&out[(long long)grow * 40 + c] = make_float2(y0, y1);
                    }
                }
            }
    }
}

// ---------------- one-shot weight conversion (all weights, fp16 transposed) --------
__global__ void convAll(const float* __restrict__ W_in,
                        const float* __restrict__ Wv0, const float* __restrict__ Wv1,
                        const float* __restrict__ W_out,
                        __half* __restrict__ Bin,
                        __half* __restrict__ Bv0, __half* __restrict__ Bv1,
                        __half* __restrict__ Wo)
{
    int idx = blockIdx.x * 256 + threadIdx.x;
    if (blockIdx.x < 512) {                       // Bin [256][512]
        int n = idx >> 9, k = idx & 511;
        Bin[idx] = __float2half(W_in[k * 256 + n]);
    } else if (blockIdx.x < 768) {                // Bv0 [256][256]
        int j = idx - 131072;
        int n = j >> 8, k = j & 255;
        Bv0[j] = __float2half(Wv0[k * 256 + n]);
    } else if (blockIdx.x < 1024) {               // Bv1 [256][256]
        int j = idx - 196608;
        int n = j >> 8, k = j & 255;
        Bv1[j] = __float2half(Wv1[k * 256 + n]);
    } else {                                      // Wo [64][256], zero-pad n>=40
        int j = idx - 262144;
        int n = j >> 8, k = j & 255;
        Wo[j] = (n < 40) ? __float2half(W_out[k * 40 + n]) : __ushort_as_half((unsigned short)0);
    }
}

// ---------------- launch ----------------
extern "C" void kernel_launch(void* const* d_in, const int* in_sizes, int n_in,
                              void* d_out, int out_size)
{
    const float* x     = (const float*)d_in[0];
    const float* W_in  = (const float*)d_in[2];
    const float* b_in  = (const float*)d_in[3];
    const float* ln0g  = (const float*)d_in[4];
    const float* ln0b  = (const float*)d_in[5];
    const float* Wv0   = (const float*)d_in[10];
    const float* bv0   = (const float*)d_in[11];
    const float* ln1g  = (const float*)d_in[12];
    const float* ln1b  = (const float*)d_in[13];
    const float* Wv1   = (const float*)d_in[18];
    const float* bv1   = (const float*)d_in[19];
    const float* ln2g  = (const float*)d_in[20];
    const float* ln2b  = (const float*)d_in[21];
    const float* W_out = (const float*)d_in[22];
    const float* b_out = (const float*)d_in[23];
    float* out = (float*)d_out;

    const int M = in_sizes[0] / 512;
    const int tiles64 = (M + 63) / 64;

    __half *pBin, *pBv0, *pBv1, *pWo;
    cudaGetSymbolAddress((void**)&pBin, g_Bin);
    cudaGetSymbolAddress((void**)&pBv0, g_Bv0);
    cudaGetSymbolAddress((void**)&pBv1, g_Bv1);
    cudaGetSymbolAddress((void**)&pWo,  g_Wo);

    cudaFuncSetAttribute(mega, cudaFuncAttributeMaxDynamicSharedMemorySize, DSMEM);

    convAll<<<1088, 256>>>(W_in, Wv0, Wv1, W_out, pBin, pBv0, pBv1, pWo);
    mega<<<tiles64, 256, DSMEM>>>(x, pBin, pBv0, pBv1, pWo,
                                  b_in, bv0, bv1, b_out,
                                  ln0g, ln0b, ln1g, ln1b, ln2g, ln2b,
                                  out, M);
}

// round 17
// speedup vs baseline: 3.6152x; 1.0611x over previous
#include <cuda_runtime.h>
#include <cuda_fp16.h>
#include <cstdint>

#define MAXN 100000

// ---------------- device scratch (weights fp16, transposed [n][k]) ----------------
__device__ __half g_Bin[256 * 512];
__device__ __half g_Bv0[256 * 256];
__device__ __half g_Bv1[256 * 256];
__device__ __half g_Wo[64 * 256];      // W_out, n padded to 64

// ---------------- PTX helpers (compute_103-safe) ----------------
__device__ __forceinline__ uint32_t smem_u32(const void* p) {
    uint32_t a;
    asm("{ .reg .u64 t; cvta.to.shared.u64 t, %1; cvt.u32.u64 %0, t; }" : "=r"(a) : "l"(p));
    return a;
}
__device__ __forceinline__ void cp16(uint32_t dst, const void* src) {
    asm volatile("cp.async.cg.shared.global [%0], [%1], 16;" :: "r"(dst), "l"(src));
}
__device__ __forceinline__ void cp_commit() {
    asm volatile("cp.async.commit_group;" ::: "memory");
}
__device__ __forceinline__ void cp_wait0() {
    asm volatile("cp.async.wait_group 0;" ::: "memory");
}
__device__ __forceinline__ void cp_wait1() {
    asm volatile("cp.async.wait_group 1;" ::: "memory");
}
__device__ __forceinline__ void ldm_x4(uint32_t* r, uint32_t addr) {
    asm volatile("ldmatrix.sync.aligned.m8n8.x4.shared.b16 {%0,%1,%2,%3}, [%4];"
        : "=r"(r[0]), "=r"(r[1]), "=r"(r[2]), "=r"(r[3]) : "r"(addr));
}
__device__ __forceinline__ void mma16816(float* c, const uint32_t* a, const uint32_t* b) {
    asm volatile("mma.sync.aligned.m16n8k16.row.col.f32.f16.f16.f32 "
        "{%0,%1,%2,%3}, {%4,%5,%6,%7}, {%8,%9}, {%0,%1,%2,%3};"
        : "+f"(c[0]), "+f"(c[1]), "+f"(c[2]), "+f"(c[3])
        : "r"(a[0]), "r"(a[1]), "r"(a[2]), "r"(a[3]), "r"(b[0]), "r"(b[1]));
}

// ---------------- SMEM map (dynamic, per CTA) ----------------
// [0, 61440)        B ring: 3 stages x 20480 (phases 1-3); phase 4: 8 x 5120 Wo tiles
// [61440, 71680)    A16: phase-1 fp16 A tile, double buffered (2 x 5120)
// [71680, 112640)   Ares: resident h, 8 tiles x 5120 (ldmatrix stage layout)
#define BSTAGE   20480
#define A16_OFF  61440
#define ARES_OFF 71680
#define DSMEM    112640

// ---------------- fused LN epilogue: bias (+residual) + LN (+relu) -> Ares ----------
// RESID=0: h = relu(LN(C+bias));  RESID=1: h = LN(0.5*(C+bias) + 0.5*h_prev)
// Ordering contract (no caller syncs needed):
//  - entry: all warps finished prior mainloop (post-mainloop __syncthreads at call site)
//  - internal sync orders ALL h_prev/Ares reads before ANY Ares writes
//  - exit: Ares writes ordered against next mainloop reads by that loop's kt=0 barrier
template<int RESID>
__device__ __forceinline__ void epilogue_ln(
    float (&acc)[2][8][4], char* dsm, float2 (*red)[4],
    const float* __restrict__ bias,
    const float* __restrict__ lng, const float* __restrict__ lnb,
    int wm, int wn, int lane)
{
    const int cbase = wn * 64 + (lane & 3) * 2;
    #pragma unroll
    for (int mt = 0; mt < 2; mt++)
        #pragma unroll
        for (int hh = 0; hh < 2; hh++) {
            int row = wm * 32 + mt * 16 + (lane >> 2) + hh * 8;
            float s = 0.f, s2 = 0.f;
            #pragma unroll
            for (int nt = 0; nt < 8; nt++) {
                int c = cbase + nt * 8;
                float2 bsv = *(const float2*)&bias[c];
                float x0 = acc[mt][nt][2 * hh], x1 = acc[mt][nt][2 * hh + 1];
                if (RESID) {
                    uint32_t hp = *(const uint32_t*)(dsm + ARES_OFF +
                        (c >> 5) * 5120 + row * 80 + (c & 31) * 2);
                    __half2 hv = *(__half2*)&hp;
                    x0 = 0.5f * (x0 + bsv.x + __half2float(hv.x));
                    x1 = 0.5f * (x1 + bsv.y + __half2float(hv.y));
                } else {
                    x0 += bsv.x; x1 += bsv.y;
                }
                acc[mt][nt][2 * hh] = x0;
                acc[mt][nt][2 * hh + 1] = x1;
                s += x0 + x1;
                s2 += x0 * x0 + x1 * x1;
            }
            s  += __shfl_xor_sync(0xffffffffu, s, 1);
            s  += __shfl_xor_sync(0xffffffffu, s, 2);
            s2 += __shfl_xor_sync(0xffffffffu, s2, 1);
            s2 += __shfl_xor_sync(0xffffffffu, s2, 2);
            if ((lane & 3) == 0) red[row][wn] = make_float2(s, s2);
        }
    __syncthreads();

    #pragma unroll
    for (int mt = 0; mt < 2; mt++)
        #pragma unroll
        for (int hh = 0; hh < 2; hh++) {
            int row = wm * 32 + mt * 16 + (lane >> 2) + hh * 8;
            float2 r0 = red[row][0], r1 = red[row][1], r2 = red[row][2], r3 = red[row][3];
            float s  = r0.x + r1.x + r2.x + r3.x;
            float s2 = r0.y + r1.y + r2.y + r3.y;
            float mu = s * (1.f / 256.f);
            float var = s2 * (1.f / 256.f) - mu * mu;
            float rstd = rsqrtf(var + 1e-5f);
            #pragma unroll
            for (int nt = 0; nt < 8; nt++) {
                int c = cbase + nt * 8;
                float2 gv = *(const float2*)&lng[c];
                float2 bv = *(const float2*)&lnb[c];
                float y0 = gv.x * (acc[mt][nt][2 * hh] - mu) * rstd + bv.x;
                float y1 = gv.y * (acc[mt][nt][2 * hh + 1] - mu) * rstd + bv.y;
                if (!RESID) { y0 = fmaxf(y0, 0.f); y1 = fmaxf(y1, 0.f); }
                __half h0 = __float2half(y0);
                __half h1 = __float2half(y1);
                uint32_t hp = (uint32_t)__half_as_ushort(h0) |
                              ((uint32_t)__half_as_ushort(h1) << 16);
                *(uint32_t*)(dsm + ARES_OFF + (c >> 5) * 5120 + row * 80 + (c & 31) * 2) = hp;
            }
        }
}

// ============ mega kernel: whole network for 64 rows per CTA ============
// phase 1: x[64,512] fp32 (register-direct LDG -> fp16 A16 dbl-buf) @ Bin^T, LN+ReLU -> Ares
// phase 2: Ares @ Bv0^T, LN+resid -> Ares
// phase 3: Ares @ Bv1^T, LN+resid -> Ares
// phase 4: Ares @ Wo^T (+b_out) -> out[64,40] fp32
// Cross-phase: next phase's first 2 B stages (or Wo) are issued BEFORE each epilogue,
// hiding the ring refill latency under the epilogue. Ring stage-0/1 overwrite is safe:
// the post-mainloop __syncthreads precedes the issue, and prior loop's last reads
// (stage kt%3 at final kt) happen before that barrier.
// 256 threads (8 warps: 2m x 4n, 32x64 warp tile), 2 CTAs/SM.
__global__ void __launch_bounds__(256, 2) mega(
    const float* __restrict__ X,
    const __half* __restrict__ Bin,
    const __half* __restrict__ Bv0, const __half* __restrict__ Bv1,
    const __half* __restrict__ Wo,
    const float* __restrict__ b_in,
    const float* __restrict__ bv0, const float* __restrict__ bv1,
    const float* __restrict__ b_out,
    const float* __restrict__ g0, const float* __restrict__ e0,
    const float* __restrict__ g1, const float* __restrict__ e1,
    const float* __restrict__ g2, const float* __restrict__ e2,
    float* __restrict__ out, int M)
{
    extern __shared__ char dsm[];
    __shared__ float2 red[64][4];
    const int tid = threadIdx.x;
    const int lane = tid & 31, wid = tid >> 5;
    const int wm = wid >> 2, wn = wid & 3;        // 2 x 4 warp grid
    const int row0 = blockIdx.x * 64;

    const uint32_t pipe = smem_u32(dsm);
    const uint32_t A16  = pipe + A16_OFF;
    const uint32_t Ares = pipe + ARES_OFF;

    const uint32_t aoff = (uint32_t)((lane & 15) * 80 + (lane >> 4) * 16);
    const uint32_t boff = (uint32_t)(((lane & 7) + ((lane >> 4) << 3)) * 80 + (((lane >> 3) & 1) << 4));
    const uint32_t awarp = (uint32_t)(wm * 32) * 80;
    const uint32_t bwarp = (uint32_t)(wn * 64) * 80;

    // per-thread B-chunk geometry for K=256 operands (phases 2/3): 1024 chunks -> 4/thread
    int rB[4], segB[4];
    uint32_t sOB[4];
    #pragma unroll
    for (int i = 0; i < 4; i++) {
        int cid = tid + i * 256;
        rB[i] = cid >> 2; segB[i] = cid & 3;
        sOB[i] = (uint32_t)(rB[i] * 80 + segB[i] * 16);
    }
    auto issueB256 = [&](const __half* B, int kt) {
        uint32_t sb = pipe + (uint32_t)(kt % 3) * BSTAGE;
        #pragma unroll
        for (int i = 0; i < 4; i++)
            cp16(sb + sOB[i], B + (long long)rB[i] * 256 + segB[i] * 8 + (long long)kt * 32);
        cp_commit();
    };

    float acc[2][8][4];
    #pragma unroll
    for (int a = 0; a < 2; a++)
        #pragma unroll
        for (int b = 0; b < 8; b++)
            #pragma unroll
            for (int c = 0; c < 4; c++) acc[a][b][c] = 0.f;

    // ============== Phase 1: x @ Bin^T (K=512, nk=16) ==============
    {
        const float* xP[2];
        uint32_t cvD[2];
        #pragma unroll
        for (int i = 0; i < 2; i++) {
            int cid = tid + i * 256;
            int r = cid >> 3, seg = cid & 7;
            int ar = min(row0 + r, M - 1);
            xP[i] = X + (long long)ar * 512 + seg * 4;
            cvD[i] = (uint32_t)(r * 80 + seg * 8);
        }
        const __half* gB[4];
        #pragma unroll
        for (int i = 0; i < 4; i++)
            gB[i] = Bin + (long long)rB[i] * 512 + segB[i] * 8;
        auto issueB1 = [&](int kt) {
            uint32_t sb = pipe + (uint32_t)(kt % 3) * BSTAGE;
            #pragma unroll
            for (int i = 0; i < 4; i++) cp16(sb + sOB[i], gB[i] + (long long)kt * 32);
            cp_commit();
        };

        float4 xr[2];
        xr[0] = *(const float4*)xP[0];
        xr[1] = *(const float4*)xP[1];
        issueB1(0);
        issueB1(1);

        for (int kt = 0; kt < 16; kt++) {
            uint32_t abuf = A16 - pipe + (uint32_t)(kt & 1) * 5120;
            #pragma unroll
            for (int i = 0; i < 2; i++) {
                __half2 p0 = __floats2half2_rn(xr[i].x, xr[i].y);
                __half2 p1 = __floats2half2_rn(xr[i].z, xr[i].w);
                *(uint2*)(dsm + abuf + cvD[i]) = make_uint2(*(uint32_t*)&p0, *(uint32_t*)&p1);
            }
            if (kt + 1 < 16) {
                xr[0] = *(const float4*)(xP[0] + (kt + 1) * 32);
                xr[1] = *(const float4*)(xP[1] + (kt + 1) * 32);
            }
            if (kt < 15) cp_wait1(); else cp_wait0();
            __syncthreads();

            uint32_t sbB = pipe + (uint32_t)(kt % 3) * BSTAGE;
            uint32_t saB = pipe + abuf;
            #pragma unroll
            for (int kk = 0; kk < 2; kk++) {
                uint32_t sa = saB + awarp + kk * 32 + aoff;
                uint32_t ah[2][4];
                ldm_x4(ah[0], sa);
                ldm_x4(ah[1], sa + 1280);
                uint32_t sB0 = sbB + bwarp + kk * 32 + boff;
                #pragma unroll
                for (int g = 0; g < 4; g++) {
                    uint32_t bh[4];
                    ldm_x4(bh, sB0 + g * 1280);
                    #pragma unroll
                    for (int mt = 0; mt < 2; mt++) {
                        mma16816(acc[mt][2 * g],     ah[mt], &bh[0]);
                        mma16816(acc[mt][2 * g + 1], ah[mt], &bh[2]);
                    }
                }
            }
            if (kt + 2 < 16) issueB1(kt + 2);
        }
    }
    // boundary 1: ring idle (phase-1 fully drained); prefetch Bv0 under epilogue
    __syncthreads();                 // protects ring stage 0/1 vs phase-1 kt=15 reads (stage 0)
    issueB256(Bv0, 0);
    issueB256(Bv0, 1);
    epilogue_ln<0>(acc, dsm, red, b_in, g0, e0, wm, wn, lane);

    // ================= Phases 2/3: h @ Bv^T (K=256, nk=8, 3-stage B-only) ==========
    auto gemm256 = [&](const __half* B) {
        #pragma unroll
        for (int a = 0; a < 2; a++)
            #pragma unroll
            for (int b = 0; b < 8; b++)
                #pragma unroll
                for (int c = 0; c < 4; c++) acc[a][b][c] = 0.f;
        for (int kt = 0; kt < 8; kt++) {
            if (kt < 7) cp_wait1(); else cp_wait0();   // pre-issued 2 + in-loop: pending = 1/0
            __syncthreads();                            // also orders prior epilogue Ares writes
            uint32_t sbB = pipe + (uint32_t)(kt % 3) * BSTAGE;
            #pragma unroll
            for (int kk = 0; kk < 2; kk++) {
                uint32_t sa = Ares + kt * 5120 + awarp + kk * 32 + aoff;
                uint32_t ah[2][4];
                ldm_x4(ah[0], sa);
                ldm_x4(ah[1], sa + 1280);
                uint32_t sB0 = sbB + bwarp + kk * 32 + boff;
                #pragma unroll
                for (int g = 0; g < 4; g++) {
                    uint32_t bh[4];
                    ldm_x4(bh, sB0 + g * 1280);
                    #pragma unroll
                    for (int mt = 0; mt < 2; mt++) {
                        mma16816(acc[mt][2 * g],     ah[mt], &bh[0]);
                        mma16816(acc[mt][2 * g + 1], ah[mt], &bh[2]);
                    }
                }
            }
            if (kt + 2 < 8) issueB256(B, kt + 2);
        }
    };

    gemm256(Bv0);
    // boundary 2: prefetch Bv1 under epilogue (phase-2 kt=7 read stage 1; sync first)
    __syncthreads();
    issueB256(Bv1, 0);
    issueB256(Bv1, 1);
    epilogue_ln<1>(acc, dsm, red, bv0, g1, e1, wm, wn, lane);

    gemm256(Bv1);
    // boundary 3: prefetch ALL of Wo (8 x 5120 = stages 0/1 region) under epilogue
    __syncthreads();
    {
        #pragma unroll
        for (int i = 0; i < 8; i++) {
            int cid = tid + i * 256;
            int t = cid >> 8;
            int c2 = cid & 255;
            int r = c2 >> 2, seg = c2 & 3;
            cp16(pipe + t * 5120 + (uint32_t)(r * 80 + seg * 16),
                 Wo + (long long)r * 256 + t * 32 + seg * 8);
        }
        cp_commit();
    }
    epilogue_ln<1>(acc, dsm, red, bv1, g2, e2, wm, wn, lane);

    // ================= Phase 4: out = h @ Wo^T + b_out =======
    cp_wait0();
    __syncthreads();    // Wo visible to all; also orders epilogue-3 Ares writes
    {
        float facc[2][2][4] = {};
        const uint32_t bwarp4 = (uint32_t)(wn * 16) * 80;
        for (int kt = 0; kt < 8; kt++) {
            #pragma unroll
            for (int kk = 0; kk < 2; kk++) {
                uint32_t sa = Ares + kt * 5120 + awarp + kk * 32 + aoff;
                uint32_t ah[2][4];
                ldm_x4(ah[0], sa);
                ldm_x4(ah[1], sa + 1280);
                uint32_t bh[4];
                ldm_x4(bh, pipe + kt * 5120 + bwarp4 + kk * 32 + boff);
                #pragma unroll
                for (int mt = 0; mt < 2; mt++) {
                    mma16816(facc[mt][0], ah[mt], &bh[0]);
                    mma16816(facc[mt][1], ah[mt], &bh[2]);
                }
            }
        }

        const int cb4 = wn * 16 + (lane & 3) * 2;
        #pragma unroll
        for (int mt = 0; mt < 2; mt++)
            #pragma unroll
            for (int hh = 0; hh < 2; hh++) {
                int grow = row0 + wm * 32 + mt * 16 + (lane >> 2) + hh * 8;
                if (grow >= M) continue;
                #pragma unroll
                for (int nt = 0; nt < 2; nt++) {
                    int c = cb4 + nt * 8;
                    if (c + 1 < 40) {
                        float2 bv = *(const float2*)&b_out[c];
                        float y0 = facc[mt][nt][2 * hh] + bv.x;
                        float y1 = facc[mt][nt][2 * hh + 1] + bv.y;
                        *(float2*)&out[(long long)grow * 40 + c] = make_float2(y0, y1);
                    }
                }
            }
    }
}

// ---------------- one-shot weight conversion (all weights, fp16 transposed) --------
__global__ void convAll(const float* __restrict__ W_in,
                        const float* __restrict__ Wv0, const float* __restrict__ Wv1,
                        const float* __restrict__ W_out,
                        __half* __restrict__ Bin,
                        __half* __restrict__ Bv0, __half* __restrict__ Bv1,
                        __half* __restrict__ Wo)
{
    int idx = blockIdx.x * 256 + threadIdx.x;
    if (blockIdx.x < 512) {                       // Bin [256][512]
        int n = idx >> 9, k = idx & 511;
        Bin[idx] = __float2half(W_in[k * 256 + n]);
    } else if (blockIdx.x < 768) {                // Bv0 [256][256]
        int j = idx - 131072;
        int n = j >> 8, k = j & 255;
        Bv0[j] = __float2half(Wv0[k * 256 + n]);
    } else if (blockIdx.x < 1024) {               // Bv1 [256][256]
        int j = idx - 196608;
        int n = j >> 8, k = j & 255;
        Bv1[j] = __float2half(Wv1[k * 256 + n]);
    } else {                                      // Wo [64][256], zero-pad n>=40
        int j = idx - 262144;
        int n = j >> 8, k = j & 255;
        Wo[j] = (n < 40) ? __float2half(W_out[k * 40 + n]) : __ushort_as_half((unsigned short)0);
    }
}

// ---------------- launch ----------------
extern "C" void kernel_launch(void* const* d_in, const int* in_sizes, int n_in,
                              void* d_out, int out_size)
{
    const float* x     = (const float*)d_in[0];
    const float* W_in  = (const float*)d_in[2];
    const float* b_in  = (const float*)d_in[3];
    const float* ln0g  = (const float*)d_in[4];
    const float* ln0b  = (const float*)d_in[5];
    const float* Wv0   = (const float*)d_in[10];
    const float* bv0   = (const float*)d_in[11];
    const float* ln1g  = (const float*)d_in[12];
    const float* ln1b  = (const float*)d_in[13];
    const float* Wv1   = (const float*)d_in[18];
    const float* bv1   = (const float*)d_in[19];
    const float* ln2g  = (const float*)d_in[20];
    const float* ln2b  = (const float*)d_in[21];
    const float* W_out = (const float*)d_in[22];
    const float* b_out = (const float*)d_in[23];
    float* out = (float*)d_out;

    const int M = in_sizes[0] / 512;
    const int tiles64 = (M + 63) / 64;

    __half *pBin, *pBv0, *pBv1, *pWo;
    cudaGetSymbolAddress((void**)&pBin, g_Bin);
    cudaGetSymbolAddress((void**)&pBv0, g_Bv0);
    cudaGetSymbolAddress((void**)&pBv1, g_Bv1);
    cudaGetSymbolAddress((void**)&pWo,  g_Wo);

    cudaFuncSetAttribute(mega, cudaFuncAttributeMaxDynamicSharedMemorySize, DSMEM);

    convAll<<<1088, 256>>>(W_in, Wv0, Wv1, W_out, pBin, pBv0, pBv1, pWo);
    mega<<<tiles64, 256, DSMEM>>>(x, pBin, pBv0, pBv1, pWo,
                                  b_in, bv0, bv1, b_out,
                                  ln0g, ln0b, ln1g, ln1b, ln2g, ln2b,
                                  out, M);
}